// round 1
// baseline (speedup 1.0000x reference)
#include <cuda_runtime.h>
#include <cuda_bf16.h>
#include <math.h>

// Problem constants
#define BB 8
#define SS 1024
#define IN_DIM 3
#define DD 512
#define HH 8
#define FF 2048
#define LL 4
#define OUTD 6
#define DH 64
#define NT (BB*SS)   // 8192 tokens

// ---------------- scratch (device globals; no allocation allowed) ----------
__device__ float g_h  [NT*DD];
__device__ float g_q  [NT*DD];
__device__ float g_k  [NT*DD];
__device__ float g_v  [NT*DD];
__device__ float g_ao [NT*DD];
__device__ float g_tmp[NT*DD];
__device__ float g_ffh[NT*FF];
__device__ float g_mask[NT];

// ---------------- block reduction helper ----------------
__device__ __forceinline__ float block_sum(float v, float* red) {
    int lane = threadIdx.x & 31, w = threadIdx.x >> 5;
    #pragma unroll
    for (int o = 16; o > 0; o >>= 1) v += __shfl_xor_sync(0xffffffffu, v, o);
    if (lane == 0) red[w] = v;
    __syncthreads();
    if (w == 0) {
        float r = (lane < (int)(blockDim.x >> 5)) ? red[lane] : 0.f;
        #pragma unroll
        for (int o = 16; o > 0; o >>= 1) r += __shfl_xor_sync(0xffffffffu, r, o);
        if (lane == 0) red[32] = r;
    }
    __syncthreads();
    return red[32];
}

// ---------------- embed: h = x@Wproj + bproj + PE ; mask ----------------
__global__ void embed_kernel(const float* __restrict__ x,
                             const float* __restrict__ Wp,
                             const float* __restrict__ bp,
                             float* __restrict__ h,
                             float* __restrict__ maskf) {
    int t = blockIdx.x;
    int s = t & (SS - 1);
    const float* xt = x + (size_t)t * IN_DIM;
    float x0 = xt[0], x1 = xt[1], x2 = xt[2];
    if (threadIdx.x == 0)
        maskf[t] = ((fabsf(x0) + fabsf(x1) + fabsf(x2)) == 0.f) ? 0.f : 1.f;
    #pragma unroll
    for (int r = 0; r < 2; r++) {
        int d = threadIdx.x + r * 256;
        float val = x0 * Wp[d] + x1 * Wp[DD + d] + x2 * Wp[2*DD + d] + bp[d];
        // PE: freq = exp(-(d rounded down to even) * ln(10000)/D)
        float freq = expf(-(float)(d & ~1) * (9.210340371976184f / (float)DD));
        float ang = (float)s * freq;
        val += (d & 1) ? cosf(ang) : sinf(ang);
        h[(size_t)t * DD + d] = val;
    }
}

// ---------------- add(optional) + layernorm, in place on h ----------------
__global__ void add_ln_kernel(float* __restrict__ h,
                              const float* __restrict__ add,
                              const float* __restrict__ g,
                              const float* __restrict__ bta) {
    __shared__ float red[40];
    int t = blockIdx.x, tid = threadIdx.x;
    float* hp = h + (size_t)t * DD;
    float v0 = hp[tid], v1 = hp[tid + 256];
    if (add) {
        v0 += add[(size_t)t * DD + tid];
        v1 += add[(size_t)t * DD + tid + 256];
    }
    float mean = block_sum(v0 + v1, red) * (1.f / (float)DD);
    float d0 = v0 - mean, d1 = v1 - mean;
    float var = block_sum(d0 * d0 + d1 * d1, red) * (1.f / (float)DD);
    float rs = rsqrtf(var + 1e-5f);
    hp[tid]       = d0 * rs * g[tid]       + bta[tid];
    hp[tid + 256] = d1 * rs * g[tid + 256] + bta[tid + 256];
}

// ---------------- generic SGEMM: C[M,N] = A[M,K] @ W[K,N] -----------------
// BM=BN=128, BK=8, 256 threads, 8x8 per thread. All dims divide evenly.
// EPI: 0 = none, 1 = silu
template <int EPI>
__global__ __launch_bounds__(256)
void sgemm_kernel(const float* __restrict__ A, const float* __restrict__ W,
                  float* __restrict__ C, int M, int N, int K) {
    const int BM = 128, BN = 128, BK = 8, TM = 8, TN = 8;
    __shared__ float As[BK][BM];
    __shared__ float Ws[BK][BN];

    A += (size_t)blockIdx.y * BM * K;
    W += (size_t)blockIdx.x * BN;
    C += (size_t)blockIdx.y * BM * N + (size_t)blockIdx.x * BN;

    int tid = threadIdx.x;
    int aRow = tid >> 1;            // 0..127
    int aCol = (tid & 1) * 4;       // 0 or 4
    int wRow = tid >> 5;            // 0..7
    int wCol = (tid & 31) * 4;      // 0..124
    int tr = (tid >> 4) * TM;       // 0..120
    int tc = (tid & 15) * TN;       // 0..120

    float acc[TM][TN];
    #pragma unroll
    for (int i = 0; i < TM; i++)
        #pragma unroll
        for (int j = 0; j < TN; j++) acc[i][j] = 0.f;

    for (int k0 = 0; k0 < K; k0 += BK) {
        float4 a4 = *reinterpret_cast<const float4*>(&A[(size_t)aRow * K + k0 + aCol]);
        As[aCol + 0][aRow] = a4.x;
        As[aCol + 1][aRow] = a4.y;
        As[aCol + 2][aRow] = a4.z;
        As[aCol + 3][aRow] = a4.w;
        float4 w4 = *reinterpret_cast<const float4*>(&W[(size_t)(k0 + wRow) * N + wCol]);
        *reinterpret_cast<float4*>(&Ws[wRow][wCol]) = w4;
        __syncthreads();

        #pragma unroll
        for (int kk = 0; kk < BK; kk++) {
            float ra[TM], rw[TN];
            float4 t0 = *reinterpret_cast<const float4*>(&As[kk][tr]);
            float4 t1 = *reinterpret_cast<const float4*>(&As[kk][tr + 4]);
            ra[0]=t0.x; ra[1]=t0.y; ra[2]=t0.z; ra[3]=t0.w;
            ra[4]=t1.x; ra[5]=t1.y; ra[6]=t1.z; ra[7]=t1.w;
            float4 u0 = *reinterpret_cast<const float4*>(&Ws[kk][tc]);
            float4 u1 = *reinterpret_cast<const float4*>(&Ws[kk][tc + 4]);
            rw[0]=u0.x; rw[1]=u0.y; rw[2]=u0.z; rw[3]=u0.w;
            rw[4]=u1.x; rw[5]=u1.y; rw[6]=u1.z; rw[7]=u1.w;
            #pragma unroll
            for (int i = 0; i < TM; i++)
                #pragma unroll
                for (int j = 0; j < TN; j++)
                    acc[i][j] = fmaf(ra[i], rw[j], acc[i][j]);
        }
        __syncthreads();
    }

    #pragma unroll
    for (int i = 0; i < TM; i++) {
        #pragma unroll
        for (int j = 0; j < TN; j += 4) {
            float4 v;
            v.x = acc[i][j+0]; v.y = acc[i][j+1]; v.z = acc[i][j+2]; v.w = acc[i][j+3];
            if (EPI == 1) {  // silu
                v.x = v.x / (1.f + __expf(-v.x));
                v.y = v.y / (1.f + __expf(-v.y));
                v.z = v.z / (1.f + __expf(-v.z));
                v.w = v.w / (1.f + __expf(-v.w));
            }
            *reinterpret_cast<float4*>(&C[(size_t)(tr + i) * N + tc + j]) = v;
        }
    }
}

// ---------------- flash attention (fp32, online softmax) ------------------
// grid: (S/128, H, B), 128 threads; one thread per query row.
__global__ __launch_bounds__(128)
void attn_kernel(const float* __restrict__ q, const float* __restrict__ k,
                 const float* __restrict__ v, const float* __restrict__ maskf,
                 float* __restrict__ out) {
    const int TK = 64;
    __shared__ float Ks[TK][DH];
    __shared__ float Vs[TK][DH];
    __shared__ float Ms[TK];

    int h = blockIdx.y, b = blockIdx.z;
    int tid = threadIdx.x;
    int qtoken = b * SS + blockIdx.x * 128 + tid;
    const float scale = 0.125f;  // 1/sqrt(64)

    float qr[DH];
    #pragma unroll
    for (int d = 0; d < DH; d += 4) {
        float4 t = *reinterpret_cast<const float4*>(&q[(size_t)qtoken * DD + h * DH + d]);
        qr[d+0] = t.x * scale; qr[d+1] = t.y * scale;
        qr[d+2] = t.z * scale; qr[d+3] = t.w * scale;
    }

    float m = -1e30f, l = 0.f;
    float o[DH];
    #pragma unroll
    for (int d = 0; d < DH; d++) o[d] = 0.f;

    for (int kt = 0; kt < SS; kt += TK) {
        __syncthreads();
        // cooperative tile load: TK*DH/4 = 1024 float4 per matrix, 8 each
        for (int i = tid; i < TK * (DH / 4); i += 128) {
            int row = i >> 4;
            int c4 = (i & 15) * 4;
            size_t goff = (size_t)(b * SS + kt + row) * DD + h * DH + c4;
            *reinterpret_cast<float4*>(&Ks[row][c4]) = *reinterpret_cast<const float4*>(&k[goff]);
            *reinterpret_cast<float4*>(&Vs[row][c4]) = *reinterpret_cast<const float4*>(&v[goff]);
        }
        if (tid < TK) Ms[tid] = maskf[b * SS + kt + tid];
        __syncthreads();

        for (int j = 0; j < TK; j++) {
            float s = 0.f;
            #pragma unroll
            for (int d = 0; d < DH; d++) s = fmaf(qr[d], Ks[j][d], s);
            s = (Ms[j] != 0.f) ? s : -1e30f;
            float mn = fmaxf(m, s);
            float alpha = __expf(m - mn);
            float p = __expf(s - mn);
            l = l * alpha + p;
            #pragma unroll
            for (int d = 0; d < DH; d++)
                o[d] = fmaf(o[d], alpha, p * Vs[j][d]);
            m = mn;
        }
    }

    float inv = 1.f / l;
    #pragma unroll
    for (int d = 0; d < DH; d += 4) {
        float4 t;
        t.x = o[d+0]*inv; t.y = o[d+1]*inv; t.z = o[d+2]*inv; t.w = o[d+3]*inv;
        *reinterpret_cast<float4*>(&out[(size_t)qtoken * DD + h * DH + d]) = t;
    }
}

// ---------------- masked mean pool + output projection --------------------
__global__ void pool_out_kernel(const float* __restrict__ h,
                                const float* __restrict__ maskf,
                                const float* __restrict__ Wout,
                                const float* __restrict__ bout,
                                float* __restrict__ out) {
    __shared__ float pooled[DD];
    __shared__ float red[40];
    int b = blockIdx.x, tid = threadIdx.x;
    float a0 = 0.f, a1 = 0.f, cnt = 0.f;
    for (int s = 0; s < SS; s++) {
        float np = maskf[b * SS + s];
        const float* hp = h + (size_t)(b * SS + s) * DD;
        a0 += hp[tid] * np;
        a1 += hp[tid + 256] * np;
        cnt += np;
    }
    float inv = 1.f / (cnt + 1e-8f);
    pooled[tid] = a0 * inv;
    pooled[tid + 256] = a1 * inv;
    __syncthreads();
    for (int j = 0; j < OUTD; j++) {
        float p = pooled[tid] * Wout[tid * OUTD + j]
                + pooled[tid + 256] * Wout[(tid + 256) * OUTD + j];
        float ssum = block_sum(p, red);
        if (tid == 0) out[b * OUTD + j] = ssum + bout[j];
    }
}

// ---------------- launch ---------------------------------------------------
extern "C" void kernel_launch(void* const* d_in, const int* in_sizes, int n_in,
                              void* d_out, int out_size) {
    const float* x     = (const float*)d_in[0];
    const float* Wproj = (const float*)d_in[1];
    const float* bproj = (const float*)d_in[2];
    const float* gp    = (const float*)d_in[3];
    const float* bp    = (const float*)d_in[4];
    const float* Wq    = (const float*)d_in[5];
    const float* Wk    = (const float*)d_in[6];
    const float* Wv    = (const float*)d_in[7];
    const float* Wo    = (const float*)d_in[8];
    const float* g1    = (const float*)d_in[9];
    const float* b1    = (const float*)d_in[10];
    const float* W1    = (const float*)d_in[11];
    const float* W2    = (const float*)d_in[12];
    const float* g2    = (const float*)d_in[13];
    const float* b2    = (const float*)d_in[14];
    const float* gf    = (const float*)d_in[15];
    const float* bf    = (const float*)d_in[16];
    const float* Wout  = (const float*)d_in[17];
    const float* bout  = (const float*)d_in[18];

    float *h, *q, *k, *v, *ao, *tmp, *ffh, *mask;
    cudaGetSymbolAddress((void**)&h,   g_h);
    cudaGetSymbolAddress((void**)&q,   g_q);
    cudaGetSymbolAddress((void**)&k,   g_k);
    cudaGetSymbolAddress((void**)&v,   g_v);
    cudaGetSymbolAddress((void**)&ao,  g_ao);
    cudaGetSymbolAddress((void**)&tmp, g_tmp);
    cudaGetSymbolAddress((void**)&ffh, g_ffh);
    cudaGetSymbolAddress((void**)&mask, g_mask);

    embed_kernel<<<NT, 256>>>(x, Wproj, bproj, h, mask);
    add_ln_kernel<<<NT, 256>>>(h, nullptr, gp, bp);

    dim3 gD(DD / 128, NT / 128);    // N=512 outputs
    dim3 gF(FF / 128, NT / 128);    // N=2048 outputs
    dim3 gAttn(SS / 128, HH, BB);

    for (int l = 0; l < LL; l++) {
        const float* wq = Wq + (size_t)l * DD * DD;
        const float* wk = Wk + (size_t)l * DD * DD;
        const float* wv = Wv + (size_t)l * DD * DD;
        const float* wo = Wo + (size_t)l * DD * DD;
        sgemm_kernel<0><<<gD, 256>>>(h, wq, q, NT, DD, DD);
        sgemm_kernel<0><<<gD, 256>>>(h, wk, k, NT, DD, DD);
        sgemm_kernel<0><<<gD, 256>>>(h, wv, v, NT, DD, DD);
        attn_kernel<<<gAttn, 128>>>(q, k, v, mask, ao);
        sgemm_kernel<0><<<gD, 256>>>(ao, wo, tmp, NT, DD, DD);
        add_ln_kernel<<<NT, 256>>>(h, tmp, g1 + l * DD, b1 + l * DD);
        sgemm_kernel<1><<<gF, 256>>>(h, W1 + (size_t)l * DD * FF, ffh, NT, FF, DD);
        sgemm_kernel<0><<<gD, 256>>>(ffh, W2 + (size_t)l * FF * DD, tmp, NT, DD, FF);
        add_ln_kernel<<<NT, 256>>>(h, tmp, g2 + l * DD, b2 + l * DD);
    }

    add_ln_kernel<<<NT, 256>>>(h, nullptr, gf, bf);
    pool_out_kernel<<<BB, 256>>>(h, mask, Wout, bout, (float*)d_out);
}

// round 3
// speedup vs baseline: 1.4627x; 1.4627x over previous
#include <cuda_runtime.h>
#include <cuda_bf16.h>
#include <math.h>
#include <stdint.h>

// Problem constants
#define BB 8
#define SS 1024
#define IN_DIM 3
#define DD 512
#define HH 8
#define FF 2048
#define LL 4
#define OUTD 6
#define DH 64
#define NT (BB*SS)   // 8192 tokens

// ======================= PTX helpers (portable, sm_80+) ====================
__device__ __forceinline__ uint32_t smem_to_u32(const void* p) {
    uint32_t a;
    asm("{ .reg .u64 t; cvta.to.shared.u64 t, %1; cvt.u32.u64 %0, t; }" : "=r"(a) : "l"(p));
    return a;
}
#define CP_ASYNC16(dst, src) \
    asm volatile("cp.async.cg.shared.global [%0], [%1], 16;" :: "r"(dst), "l"(src))
#define CP_COMMIT() asm volatile("cp.async.commit_group;" ::: "memory")
#define CP_WAIT(n)  asm volatile("cp.async.wait_group %0;" :: "n"(n) : "memory")

__device__ __forceinline__ void ldm_x4(uint32_t* r, uint32_t addr) {
    asm volatile("ldmatrix.sync.aligned.m8n8.x4.shared.b16 {%0,%1,%2,%3}, [%4];"
        : "=r"(r[0]), "=r"(r[1]), "=r"(r[2]), "=r"(r[3]) : "r"(addr));
}
__device__ __forceinline__ void mma_bf16(float* d, const uint32_t* a, const uint32_t* b) {
    asm volatile("mma.sync.aligned.m16n8k16.row.col.f32.bf16.bf16.f32 "
        "{%0,%1,%2,%3}, {%4,%5,%6,%7}, {%8,%9}, {%0,%1,%2,%3};"
        : "+f"(d[0]), "+f"(d[1]), "+f"(d[2]), "+f"(d[3])
        : "r"(a[0]), "r"(a[1]), "r"(a[2]), "r"(a[3]), "r"(b[0]), "r"(b[1]));
}

// ---------------- scratch (device globals; no allocation allowed) ----------
__device__ float g_h  [NT*DD];
__device__ float g_q  [NT*DD];
__device__ float g_k  [NT*DD];
__device__ float g_v  [NT*DD];
__device__ float g_tmp[NT*DD];
__device__ float g_mask[NT];
// bf16 split activations
__device__ __nv_bfloat16 g_hh [NT*DD], g_hl [NT*DD];
__device__ __nv_bfloat16 g_aoh[NT*DD], g_aol[NT*DD];
__device__ __nv_bfloat16 g_fh [NT*FF], g_fl [NT*FF];
// bf16 split, transposed weights [N, K]
__device__ __nv_bfloat16 g_wqh[LL*DD*DD], g_wql[LL*DD*DD];
__device__ __nv_bfloat16 g_wkh[LL*DD*DD], g_wkl[LL*DD*DD];
__device__ __nv_bfloat16 g_wvh[LL*DD*DD], g_wvl[LL*DD*DD];
__device__ __nv_bfloat16 g_woh[LL*DD*DD], g_wol[LL*DD*DD];
__device__ __nv_bfloat16 g_w1h[LL*FF*DD], g_w1l[LL*FF*DD];
__device__ __nv_bfloat16 g_w2h[LL*DD*FF], g_w2l[LL*DD*FF];

__device__ __forceinline__ void split_bf16(float v, __nv_bfloat16& hi, __nv_bfloat16& lo) {
    hi = __float2bfloat16(v);
    lo = __float2bfloat16(v - __bfloat162float(hi));
}

// ---------------- block reduction helper ----------------
__device__ __forceinline__ float block_sum(float v, float* red) {
    int lane = threadIdx.x & 31, w = threadIdx.x >> 5;
    #pragma unroll
    for (int o = 16; o > 0; o >>= 1) v += __shfl_xor_sync(0xffffffffu, v, o);
    if (lane == 0) red[w] = v;
    __syncthreads();
    if (w == 0) {
        float r = (lane < (int)(blockDim.x >> 5)) ? red[lane] : 0.f;
        #pragma unroll
        for (int o = 16; o > 0; o >>= 1) r += __shfl_xor_sync(0xffffffffu, r, o);
        if (lane == 0) red[32] = r;
    }
    __syncthreads();
    return red[32];
}

// ---------------- weight prep: W[K,N] fp32 -> Th[N,K], Tl[N,K] bf16 --------
__global__ void wprep_kernel(const float* __restrict__ W,
                             __nv_bfloat16* __restrict__ Th,
                             __nv_bfloat16* __restrict__ Tl, int K, int N) {
    __shared__ float tile[32][33];
    int tx = threadIdx.x, ty = threadIdx.y;
    int n0 = blockIdx.x * 32, k0 = blockIdx.y * 32;
    #pragma unroll
    for (int j = 0; j < 32; j += 8)
        tile[ty + j][tx] = W[(size_t)(k0 + ty + j) * N + n0 + tx];
    __syncthreads();
    #pragma unroll
    for (int j = 0; j < 32; j += 8) {
        float v = tile[tx][ty + j];
        __nv_bfloat16 hi, lo; split_bf16(v, hi, lo);
        size_t idx = (size_t)(n0 + ty + j) * K + k0 + tx;
        Th[idx] = hi; Tl[idx] = lo;
    }
}

// ---------------- embed: h = x@Wproj + bproj + PE ; mask ----------------
__global__ void embed_kernel(const float* __restrict__ x,
                             const float* __restrict__ Wp,
                             const float* __restrict__ bp,
                             float* __restrict__ h,
                             float* __restrict__ maskf) {
    int t = blockIdx.x;
    int s = t & (SS - 1);
    const float* xt = x + (size_t)t * IN_DIM;
    float x0 = xt[0], x1 = xt[1], x2 = xt[2];
    if (threadIdx.x == 0)
        maskf[t] = ((fabsf(x0) + fabsf(x1) + fabsf(x2)) == 0.f) ? 0.f : 1.f;
    #pragma unroll
    for (int r = 0; r < 2; r++) {
        int d = threadIdx.x + r * 256;
        float val = x0 * Wp[d] + x1 * Wp[DD + d] + x2 * Wp[2*DD + d] + bp[d];
        float freq = expf(-(float)(d & ~1) * (9.210340371976184f / (float)DD));
        float ang = (float)s * freq;
        val += (d & 1) ? cosf(ang) : sinf(ang);
        h[(size_t)t * DD + d] = val;
    }
}

// ------- add(optional) + layernorm, in place on h; emits bf16 hi/lo -------
__global__ void add_ln_kernel(float* __restrict__ h,
                              const float* __restrict__ add,
                              const float* __restrict__ g,
                              const float* __restrict__ bta,
                              __nv_bfloat16* __restrict__ oh,
                              __nv_bfloat16* __restrict__ ol) {
    __shared__ float red[40];
    int t = blockIdx.x, tid = threadIdx.x;
    float* hp = h + (size_t)t * DD;
    float v0 = hp[tid], v1 = hp[tid + 256];
    if (add) {
        v0 += add[(size_t)t * DD + tid];
        v1 += add[(size_t)t * DD + tid + 256];
    }
    float mean = block_sum(v0 + v1, red) * (1.f / (float)DD);
    float d0 = v0 - mean, d1 = v1 - mean;
    float var = block_sum(d0 * d0 + d1 * d1, red) * (1.f / (float)DD);
    float rs = rsqrtf(var + 1e-5f);
    float y0 = d0 * rs * g[tid]       + bta[tid];
    float y1 = d1 * rs * g[tid + 256] + bta[tid + 256];
    hp[tid] = y0; hp[tid + 256] = y1;
    __nv_bfloat16 hi, lo;
    split_bf16(y0, hi, lo); oh[(size_t)t*DD + tid] = hi;       ol[(size_t)t*DD + tid] = lo;
    split_bf16(y1, hi, lo); oh[(size_t)t*DD + tid + 256] = hi; ol[(size_t)t*DD + tid + 256] = lo;
}

// =================== warp-MMA split-bf16 GEMM ==============================
// C[M,N] = A[M,K] @ W[K,N], A given as (Ah+Al) bf16, W transposed as
// Bt[N,K] = (Bh+Bl) bf16.  D = AhBh + AlBh + AhBl accumulated in fp32.
// 128x128 CTA tile, 8 warps (each 32x64), BK=32, cp.async double buffering.
// EPI 0: fp32 C.  EPI 1: silu -> bf16 hi/lo (Chi, Clo).
#define SMEM_STRIDE 80          // bytes per row (32 bf16 + 8 pad)
#define MAT_BYTES   10240       // 128 rows * 80B
#define BUF_BYTES   40960       // 4 matrices
#define GEMM_SMEM   (2*BUF_BYTES)

template <int EPI>
__global__ __launch_bounds__(256)
void gemm_mma(const __nv_bfloat16* __restrict__ Ah, const __nv_bfloat16* __restrict__ Al,
              const __nv_bfloat16* __restrict__ Bh, const __nv_bfloat16* __restrict__ Bl,
              float* __restrict__ C,
              __nv_bfloat16* __restrict__ Chi, __nv_bfloat16* __restrict__ Clo,
              int M, int N, int K) {
    extern __shared__ char smem[];
    const int tid = threadIdx.x, lane = tid & 31, wid = tid >> 5;
    const int mBase = blockIdx.y * 128, nBase = blockIdx.x * 128;
    const int wm = wid >> 1, wn = wid & 1;     // warp tile: rows wm*32, cols wn*64
    uint32_t sbase = smem_to_u32(smem);

    float acc[2][8][4];
    #pragma unroll
    for (int i = 0; i < 2; i++)
        #pragma unroll
        for (int j = 0; j < 8; j++)
            #pragma unroll
            for (int e = 0; e < 4; e++) acc[i][j][e] = 0.f;

    const int nChunks = K >> 5;

    // load mapping: 512 16B-pieces per matrix, thread does pieces 2t, 2t+1
    int idx0 = tid << 1;
    int r0 = idx0 >> 2, p0 = idx0 & 3;
    int r1 = r0, p1 = p0 + 1;                  // idx0 even => same row

    // ldmatrix lane addressing
    int aRow  = lane & 15;
    int aHalf = lane >> 4;                     // +16B (k8..15)
    int bN    = (lane & 7) | ((lane & 16) >> 1);
    int bHalf = (lane >> 3) & 1;

    const __nv_bfloat16* gmat[4] = {Ah, Al, Bh, Bl};
    int rbase[4] = {mBase, mBase, nBase, nBase};

#define PRELOAD(c) do { \
    int _b = (c) & 1; \
    uint32_t _dst = sbase + _b * BUF_BYTES; \
    int _kc = (c) << 5; \
    _Pragma("unroll") \
    for (int _m = 0; _m < 4; _m++) { \
        const char* _g = (const char*)(gmat[_m] + (size_t)(rbase[_m] + r0) * K + _kc); \
        uint32_t _d = _dst + _m * MAT_BYTES + r0 * SMEM_STRIDE; \
        CP_ASYNC16(_d + p0 * 16, _g + p0 * 16); \
        CP_ASYNC16(_d + p1 * 16, _g + p1 * 16); \
    } \
} while (0)

    PRELOAD(0);
    CP_COMMIT();

    for (int c = 0; c < nChunks; c++) {
        if (c + 1 < nChunks) { PRELOAD(c + 1); CP_COMMIT(); CP_WAIT(1); }
        else                 { CP_WAIT(0); }
        __syncthreads();

        uint32_t bufb   = sbase + (c & 1) * BUF_BYTES;
        uint32_t aHbase = bufb + (wm * 32) * SMEM_STRIDE;
        uint32_t aLbase = aHbase + MAT_BYTES;
        uint32_t bHbase = bufb + 2 * MAT_BYTES + (wn * 64) * SMEM_STRIDE;
        uint32_t bLbase = bHbase + MAT_BYTES;

        #pragma unroll
        for (int ks = 0; ks < 2; ks++) {
            int koff = ks * 32 + aHalf * 16;
            uint32_t ah[2][4], al[2][4];
            #pragma unroll
            for (int mi = 0; mi < 2; mi++) {
                uint32_t off = (mi * 16 + aRow) * SMEM_STRIDE + koff;
                ldm_x4(ah[mi], aHbase + off);
                ldm_x4(al[mi], aLbase + off);
            }
            int koffb = ks * 32 + bHalf * 16;
            #pragma unroll
            for (int np = 0; np < 4; np++) {
                uint32_t off = (np * 16 + bN) * SMEM_STRIDE + koffb;
                uint32_t bh[4], bl[4];
                ldm_x4(bh, bHbase + off);
                ldm_x4(bl, bLbase + off);
                #pragma unroll
                for (int mi = 0; mi < 2; mi++) {
                    mma_bf16(acc[mi][np*2],   ah[mi], bh);
                    mma_bf16(acc[mi][np*2+1], ah[mi], bh + 2);
                    mma_bf16(acc[mi][np*2],   al[mi], bh);
                    mma_bf16(acc[mi][np*2+1], al[mi], bh + 2);
                    mma_bf16(acc[mi][np*2],   ah[mi], bl);
                    mma_bf16(acc[mi][np*2+1], ah[mi], bl + 2);
                }
            }
        }
        __syncthreads();
    }

    // epilogue
    int rowb = mBase + wm * 32 + (lane >> 2);
    int colb = nBase + wn * 64 + (lane & 3) * 2;
    #pragma unroll
    for (int mi = 0; mi < 2; mi++) {
        #pragma unroll
        for (int ns = 0; ns < 8; ns++) {
            int row = rowb + mi * 16;
            int col = colb + ns * 8;
            float c0 = acc[mi][ns][0], c1 = acc[mi][ns][1];
            float c2 = acc[mi][ns][2], c3 = acc[mi][ns][3];
            if (EPI == 0) {
                *reinterpret_cast<float2*>(C + (size_t)row * N + col)       = make_float2(c0, c1);
                *reinterpret_cast<float2*>(C + (size_t)(row + 8) * N + col) = make_float2(c2, c3);
            } else {
                c0 = c0 / (1.f + __expf(-c0)); c1 = c1 / (1.f + __expf(-c1));
                c2 = c2 / (1.f + __expf(-c2)); c3 = c3 / (1.f + __expf(-c3));
                __nv_bfloat16 h0,l0,h1,l1,h2,l2,h3,l3;
                split_bf16(c0,h0,l0); split_bf16(c1,h1,l1);
                split_bf16(c2,h2,l2); split_bf16(c3,h3,l3);
                *reinterpret_cast<__nv_bfloat162*>(Chi + (size_t)row * N + col)       = __nv_bfloat162(h0, h1);
                *reinterpret_cast<__nv_bfloat162*>(Clo + (size_t)row * N + col)       = __nv_bfloat162(l0, l1);
                *reinterpret_cast<__nv_bfloat162*>(Chi + (size_t)(row + 8) * N + col) = __nv_bfloat162(h2, h3);
                *reinterpret_cast<__nv_bfloat162*>(Clo + (size_t)(row + 8) * N + col) = __nv_bfloat162(l2, l3);
            }
        }
    }
#undef PRELOAD
}

// ---------------- flash attention (fp32, online softmax) ------------------
__global__ __launch_bounds__(128)
void attn_kernel(const float* __restrict__ q, const float* __restrict__ k,
                 const float* __restrict__ v, const float* __restrict__ maskf,
                 __nv_bfloat16* __restrict__ outh, __nv_bfloat16* __restrict__ outl) {
    const int TK = 64;
    __shared__ float Ks[TK][DH];
    __shared__ float Vs[TK][DH];
    __shared__ float Ms[TK];

    int h = blockIdx.y, b = blockIdx.z;
    int tid = threadIdx.x;
    int qtoken = b * SS + blockIdx.x * 128 + tid;
    const float scale = 0.125f;

    float qr[DH];
    #pragma unroll
    for (int d = 0; d < DH; d += 4) {
        float4 t = *reinterpret_cast<const float4*>(&q[(size_t)qtoken * DD + h * DH + d]);
        qr[d+0] = t.x * scale; qr[d+1] = t.y * scale;
        qr[d+2] = t.z * scale; qr[d+3] = t.w * scale;
    }

    float m = -1e30f, l = 0.f;
    float o[DH];
    #pragma unroll
    for (int d = 0; d < DH; d++) o[d] = 0.f;

    for (int kt = 0; kt < SS; kt += TK) {
        __syncthreads();
        for (int i = tid; i < TK * (DH / 4); i += 128) {
            int row = i >> 4;
            int c4 = (i & 15) * 4;
            size_t goff = (size_t)(b * SS + kt + row) * DD + h * DH + c4;
            *reinterpret_cast<float4*>(&Ks[row][c4]) = *reinterpret_cast<const float4*>(&k[goff]);
            *reinterpret_cast<float4*>(&Vs[row][c4]) = *reinterpret_cast<const float4*>(&v[goff]);
        }
        if (tid < TK) Ms[tid] = maskf[b * SS + kt + tid];
        __syncthreads();

        for (int j = 0; j < TK; j++) {
            float s = 0.f;
            #pragma unroll
            for (int d = 0; d < DH; d++) s = fmaf(qr[d], Ks[j][d], s);
            s = (Ms[j] != 0.f) ? s : -1e30f;
            float mn = fmaxf(m, s);
            float alpha = __expf(m - mn);
            float p = __expf(s - mn);
            l = l * alpha + p;
            #pragma unroll
            for (int d = 0; d < DH; d++)
                o[d] = fmaf(o[d], alpha, p * Vs[j][d]);
            m = mn;
        }
    }

    float inv = 1.f / l;
    size_t obase = (size_t)qtoken * DD + h * DH;
    #pragma unroll
    for (int d = 0; d < DH; d += 2) {
        float f0 = o[d] * inv, f1 = o[d+1] * inv;
        __nv_bfloat16 h0, l0, h1, l1;
        split_bf16(f0, h0, l0); split_bf16(f1, h1, l1);
        *reinterpret_cast<__nv_bfloat162*>(outh + obase + d) = __nv_bfloat162(h0, h1);
        *reinterpret_cast<__nv_bfloat162*>(outl + obase + d) = __nv_bfloat162(l0, l1);
    }
}

// ---------------- masked mean pool + output projection --------------------
__global__ void pool_out_kernel(const float* __restrict__ h,
                                const float* __restrict__ maskf,
                                const float* __restrict__ Wout,
                                const float* __restrict__ bout,
                                float* __restrict__ out) {
    __shared__ float pooled[DD];
    __shared__ float red[40];
    int b = blockIdx.x, tid = threadIdx.x;
    float a0 = 0.f, a1 = 0.f, cnt = 0.f;
    for (int s = 0; s < SS; s++) {
        float np = maskf[b * SS + s];
        const float* hp = h + (size_t)(b * SS + s) * DD;
        a0 += hp[tid] * np;
        a1 += hp[tid + 256] * np;
        cnt += np;
    }
    float inv = 1.f / (cnt + 1e-8f);
    pooled[tid] = a0 * inv;
    pooled[tid + 256] = a1 * inv;
    __syncthreads();
    for (int j = 0; j < OUTD; j++) {
        float p = pooled[tid] * Wout[tid * OUTD + j]
                + pooled[tid + 256] * Wout[(tid + 256) * OUTD + j];
        float ssum = block_sum(p, red);
        if (tid == 0) out[b * OUTD + j] = ssum + bout[j];
    }
}

// ---------------- launch ---------------------------------------------------
extern "C" void kernel_launch(void* const* d_in, const int* in_sizes, int n_in,
                              void* d_out, int out_size) {
    const float* x     = (const float*)d_in[0];
    const float* Wproj = (const float*)d_in[1];
    const float* bproj = (const float*)d_in[2];
    const float* gp    = (const float*)d_in[3];
    const float* bp    = (const float*)d_in[4];
    const float* Wq    = (const float*)d_in[5];
    const float* Wk    = (const float*)d_in[6];
    const float* Wv    = (const float*)d_in[7];
    const float* Wo    = (const float*)d_in[8];
    const float* g1    = (const float*)d_in[9];
    const float* b1    = (const float*)d_in[10];
    const float* W1    = (const float*)d_in[11];
    const float* W2    = (const float*)d_in[12];
    const float* g2    = (const float*)d_in[13];
    const float* b2    = (const float*)d_in[14];
    const float* gf    = (const float*)d_in[15];
    const float* bf    = (const float*)d_in[16];
    const float* Wout  = (const float*)d_in[17];
    const float* bout  = (const float*)d_in[18];

    float *h, *q, *k, *v, *tmp, *mask;
    cudaGetSymbolAddress((void**)&h,    g_h);
    cudaGetSymbolAddress((void**)&q,    g_q);
    cudaGetSymbolAddress((void**)&k,    g_k);
    cudaGetSymbolAddress((void**)&v,    g_v);
    cudaGetSymbolAddress((void**)&tmp,  g_tmp);
    cudaGetSymbolAddress((void**)&mask, g_mask);
    __nv_bfloat16 *hh, *hl, *aoh, *aol, *fh, *fl;
    cudaGetSymbolAddress((void**)&hh,  g_hh);  cudaGetSymbolAddress((void**)&hl,  g_hl);
    cudaGetSymbolAddress((void**)&aoh, g_aoh); cudaGetSymbolAddress((void**)&aol, g_aol);
    cudaGetSymbolAddress((void**)&fh,  g_fh);  cudaGetSymbolAddress((void**)&fl,  g_fl);
    __nv_bfloat16 *wqh,*wql,*wkh,*wkl,*wvh,*wvl,*woh,*wol,*w1h,*w1l,*w2h,*w2l;
    cudaGetSymbolAddress((void**)&wqh, g_wqh); cudaGetSymbolAddress((void**)&wql, g_wql);
    cudaGetSymbolAddress((void**)&wkh, g_wkh); cudaGetSymbolAddress((void**)&wkl, g_wkl);
    cudaGetSymbolAddress((void**)&wvh, g_wvh); cudaGetSymbolAddress((void**)&wvl, g_wvl);
    cudaGetSymbolAddress((void**)&woh, g_woh); cudaGetSymbolAddress((void**)&wol, g_wol);
    cudaGetSymbolAddress((void**)&w1h, g_w1h); cudaGetSymbolAddress((void**)&w1l, g_w1l);
    cudaGetSymbolAddress((void**)&w2h, g_w2h); cudaGetSymbolAddress((void**)&w2l, g_w2l);

    cudaFuncSetAttribute(gemm_mma<0>, cudaFuncAttributeMaxDynamicSharedMemorySize, GEMM_SMEM);
    cudaFuncSetAttribute(gemm_mma<1>, cudaFuncAttributeMaxDynamicSharedMemorySize, GEMM_SMEM);

    // weight prep (transpose + bf16 split)
    dim3 tb(32, 8);
    dim3 gDDp(DD/32, DD/32), gW1p(FF/32, DD/32), gW2p(DD/32, FF/32);
    for (int l = 0; l < LL; l++) {
        size_t od = (size_t)l * DD * DD, of1 = (size_t)l * FF * DD, of2 = (size_t)l * DD * FF;
        wprep_kernel<<<gDDp, tb>>>(Wq + od, wqh + od, wql + od, DD, DD);
        wprep_kernel<<<gDDp, tb>>>(Wk + od, wkh + od, wkl + od, DD, DD);
        wprep_kernel<<<gDDp, tb>>>(Wv + od, wvh + od, wvl + od, DD, DD);
        wprep_kernel<<<gDDp, tb>>>(Wo + od, woh + od, wol + od, DD, DD);
        wprep_kernel<<<gW1p, tb>>>(W1 + of1, w1h + of1, w1l + of1, DD, FF);
        wprep_kernel<<<gW2p, tb>>>(W2 + of2, w2h + of2, w2l + of2, FF, DD);
    }

    embed_kernel<<<NT, 256>>>(x, Wproj, bproj, h, mask);
    add_ln_kernel<<<NT, 256>>>(h, nullptr, gp, bp, hh, hl);

    dim3 gQ(DD / 128, NT / 128);
    dim3 gF1(FF / 128, NT / 128);
    dim3 gAttn(SS / 128, HH, BB);

    for (int l = 0; l < LL; l++) {
        size_t od = (size_t)l * DD * DD, of1 = (size_t)l * FF * DD, of2 = (size_t)l * DD * FF;
        gemm_mma<0><<<gQ, 256, GEMM_SMEM>>>(hh, hl, wqh + od, wql + od, q, nullptr, nullptr, NT, DD, DD);
        gemm_mma<0><<<gQ, 256, GEMM_SMEM>>>(hh, hl, wkh + od, wkl + od, k, nullptr, nullptr, NT, DD, DD);
        gemm_mma<0><<<gQ, 256, GEMM_SMEM>>>(hh, hl, wvh + od, wvl + od, v, nullptr, nullptr, NT, DD, DD);
        attn_kernel<<<gAttn, 128>>>(q, k, v, mask, aoh, aol);
        gemm_mma<0><<<gQ, 256, GEMM_SMEM>>>(aoh, aol, woh + od, wol + od, tmp, nullptr, nullptr, NT, DD, DD);
        add_ln_kernel<<<NT, 256>>>(h, tmp, g1 + l * DD, b1 + l * DD, hh, hl);
        gemm_mma<1><<<gF1, 256, GEMM_SMEM>>>(hh, hl, w1h + of1, w1l + of1, nullptr, fh, fl, NT, FF, DD);
        gemm_mma<0><<<gQ, 256, GEMM_SMEM>>>(fh, fl, w2h + of2, w2l + of2, tmp, nullptr, nullptr, NT, DD, FF);
        add_ln_kernel<<<NT, 256>>>(h, tmp, g2 + l * DD, b2 + l * DD, hh, hl);
    }

    add_ln_kernel<<<NT, 256>>>(h, nullptr, gf, bf, hh, hl);
    pool_out_kernel<<<BB, 256>>>(h, mask, Wout, bout, (float*)d_out);
}

// round 4
// speedup vs baseline: 2.3357x; 1.5969x over previous
#include <cuda_runtime.h>
#include <cuda_bf16.h>
#include <math.h>
#include <stdint.h>

// Problem constants
#define BB 8
#define SS 1024
#define IN_DIM 3
#define DD 512
#define HH 8
#define FF 2048
#define LL 4
#define OUTD 6
#define DH 64
#define NT (BB*SS)   // 8192 tokens

// ======================= PTX helpers (portable, sm_80+) ====================
__device__ __forceinline__ uint32_t smem_to_u32(const void* p) {
    uint32_t a;
    asm("{ .reg .u64 t; cvta.to.shared.u64 t, %1; cvt.u32.u64 %0, t; }" : "=r"(a) : "l"(p));
    return a;
}
#define CP_ASYNC16(dst, src) \
    asm volatile("cp.async.cg.shared.global [%0], [%1], 16;" :: "r"(dst), "l"(src))
#define CP_ASYNC4(dst, src) \
    asm volatile("cp.async.ca.shared.global [%0], [%1], 4;" :: "r"(dst), "l"(src))
#define CP_COMMIT() asm volatile("cp.async.commit_group;" ::: "memory")
#define CP_WAIT(n)  asm volatile("cp.async.wait_group %0;" :: "n"(n) : "memory")

__device__ __forceinline__ void ldm_x4(uint32_t* r, uint32_t addr) {
    asm volatile("ldmatrix.sync.aligned.m8n8.x4.shared.b16 {%0,%1,%2,%3}, [%4];"
        : "=r"(r[0]), "=r"(r[1]), "=r"(r[2]), "=r"(r[3]) : "r"(addr));
}
__device__ __forceinline__ void ldm_x4_t(uint32_t* r, uint32_t addr) {
    asm volatile("ldmatrix.sync.aligned.m8n8.x4.trans.shared.b16 {%0,%1,%2,%3}, [%4];"
        : "=r"(r[0]), "=r"(r[1]), "=r"(r[2]), "=r"(r[3]) : "r"(addr));
}
__device__ __forceinline__ void mma_bf16(float* d, const uint32_t* a, const uint32_t* b) {
    asm volatile("mma.sync.aligned.m16n8k16.row.col.f32.bf16.bf16.f32 "
        "{%0,%1,%2,%3}, {%4,%5,%6,%7}, {%8,%9}, {%0,%1,%2,%3};"
        : "+f"(d[0]), "+f"(d[1]), "+f"(d[2]), "+f"(d[3])
        : "r"(a[0]), "r"(a[1]), "r"(a[2]), "r"(a[3]), "r"(b[0]), "r"(b[1]));
}

// ---------------- scratch (device globals; no allocation allowed) ----------
__device__ float g_h  [NT*DD];
__device__ float g_tmp[NT*DD];
__device__ float g_mask[NT];
__device__ float g_pool[BB*16*DD];
__device__ float g_cnt[BB*16];
// bf16 split activations
__device__ __nv_bfloat16 g_hh [NT*DD], g_hl [NT*DD];
__device__ __nv_bfloat16 g_aoh[NT*DD], g_aol[NT*DD];
__device__ __nv_bfloat16 g_fh [NT*FF], g_fl [NT*FF];
__device__ __nv_bfloat16 g_qh[NT*DD], g_ql[NT*DD];
__device__ __nv_bfloat16 g_kh[NT*DD], g_kl[NT*DD];
__device__ __nv_bfloat16 g_vh[NT*DD], g_vl[NT*DD];
// bf16 split, transposed weights [N, K]
__device__ __nv_bfloat16 g_wqh[LL*DD*DD], g_wql[LL*DD*DD];
__device__ __nv_bfloat16 g_wkh[LL*DD*DD], g_wkl[LL*DD*DD];
__device__ __nv_bfloat16 g_wvh[LL*DD*DD], g_wvl[LL*DD*DD];
__device__ __nv_bfloat16 g_woh[LL*DD*DD], g_wol[LL*DD*DD];
__device__ __nv_bfloat16 g_w1h[LL*FF*DD], g_w1l[LL*FF*DD];
__device__ __nv_bfloat16 g_w2h[LL*DD*FF], g_w2l[LL*DD*FF];

__device__ __forceinline__ void split_bf16(float v, __nv_bfloat16& hi, __nv_bfloat16& lo) {
    hi = __float2bfloat16(v);
    lo = __float2bfloat16(v - __bfloat162float(hi));
}
__device__ __forceinline__ uint32_t packpair(float a, float b) {
    __nv_bfloat162 t(__float2bfloat16(a), __float2bfloat16(b));
    return *reinterpret_cast<uint32_t*>(&t);
}
__device__ __forceinline__ float bres(float x) {
    return x - __bfloat162float(__float2bfloat16(x));
}
__device__ __forceinline__ uint32_t hscale8(uint32_t x) {  // *0.125 exact
    __nv_bfloat162 v = *reinterpret_cast<__nv_bfloat162*>(&x);
    __nv_bfloat162 s = __float2bfloat162_rn(0.125f);
    v = __hmul2(v, s);
    return *reinterpret_cast<uint32_t*>(&v);
}

// ---------------- block reduction helper ----------------
__device__ __forceinline__ float block_sum(float v, float* red) {
    int lane = threadIdx.x & 31, w = threadIdx.x >> 5;
    #pragma unroll
    for (int o = 16; o > 0; o >>= 1) v += __shfl_xor_sync(0xffffffffu, v, o);
    if (lane == 0) red[w] = v;
    __syncthreads();
    if (w == 0) {
        float r = (lane < (int)(blockDim.x >> 5)) ? red[lane] : 0.f;
        #pragma unroll
        for (int o = 16; o > 0; o >>= 1) r += __shfl_xor_sync(0xffffffffu, r, o);
        if (lane == 0) red[32] = r;
    }
    __syncthreads();
    return red[32];
}

// ---------------- weight prep: W[K,N] fp32 -> Th[N,K], Tl[N,K] bf16 --------
__global__ void wprep_kernel(const float* __restrict__ W,
                             __nv_bfloat16* __restrict__ Th,
                             __nv_bfloat16* __restrict__ Tl, int K, int N) {
    __shared__ float tile[32][33];
    int tx = threadIdx.x, ty = threadIdx.y;
    int n0 = blockIdx.x * 32, k0 = blockIdx.y * 32;
    #pragma unroll
    for (int j = 0; j < 32; j += 8)
        tile[ty + j][tx] = W[(size_t)(k0 + ty + j) * N + n0 + tx];
    __syncthreads();
    #pragma unroll
    for (int j = 0; j < 32; j += 8) {
        float v = tile[tx][ty + j];
        __nv_bfloat16 hi, lo; split_bf16(v, hi, lo);
        size_t idx = (size_t)(n0 + ty + j) * K + k0 + tx;
        Th[idx] = hi; Tl[idx] = lo;
    }
}

// ---------------- embed: h = x@Wproj + bproj + PE ; mask ----------------
__global__ void embed_kernel(const float* __restrict__ x,
                             const float* __restrict__ Wp,
                             const float* __restrict__ bp,
                             float* __restrict__ h,
                             float* __restrict__ maskf) {
    int t = blockIdx.x;
    int s = t & (SS - 1);
    const float* xt = x + (size_t)t * IN_DIM;
    float x0 = xt[0], x1 = xt[1], x2 = xt[2];
    if (threadIdx.x == 0)
        maskf[t] = ((fabsf(x0) + fabsf(x1) + fabsf(x2)) == 0.f) ? 0.f : 1.f;
    #pragma unroll
    for (int r = 0; r < 2; r++) {
        int d = threadIdx.x + r * 256;
        float val = x0 * Wp[d] + x1 * Wp[DD + d] + x2 * Wp[2*DD + d] + bp[d];
        float freq = expf(-(float)(d & ~1) * (9.210340371976184f / (float)DD));
        float ang = (float)s * freq;
        val += (d & 1) ? cosf(ang) : sinf(ang);
        h[(size_t)t * DD + d] = val;
    }
}

// ------- add(optional) + layernorm, in place on h; emits bf16 hi/lo -------
__global__ void add_ln_kernel(float* __restrict__ h,
                              const float* __restrict__ add,
                              const float* __restrict__ g,
                              const float* __restrict__ bta,
                              __nv_bfloat16* __restrict__ oh,
                              __nv_bfloat16* __restrict__ ol) {
    __shared__ float red[40];
    int t = blockIdx.x, tid = threadIdx.x;
    float* hp = h + (size_t)t * DD;
    float v0 = hp[tid], v1 = hp[tid + 256];
    if (add) {
        v0 += add[(size_t)t * DD + tid];
        v1 += add[(size_t)t * DD + tid + 256];
    }
    float mean = block_sum(v0 + v1, red) * (1.f / (float)DD);
    float d0 = v0 - mean, d1 = v1 - mean;
    float var = block_sum(d0 * d0 + d1 * d1, red) * (1.f / (float)DD);
    float rs = rsqrtf(var + 1e-5f);
    float y0 = d0 * rs * g[tid]       + bta[tid];
    float y1 = d1 * rs * g[tid + 256] + bta[tid + 256];
    hp[tid] = y0; hp[tid + 256] = y1;
    __nv_bfloat16 hi, lo;
    split_bf16(y0, hi, lo); oh[(size_t)t*DD + tid] = hi;       ol[(size_t)t*DD + tid] = lo;
    split_bf16(y1, hi, lo); oh[(size_t)t*DD + tid + 256] = hi; ol[(size_t)t*DD + tid + 256] = lo;
}

// =================== warp-MMA split-bf16 GEMM ==============================
// EPI 0: fp32 C.  EPI 1: silu -> bf16 hi/lo.  EPI 2: bf16 hi/lo (no act).
#define SMEM_STRIDE 80          // bytes per row (32 bf16 + 8 pad)
#define MAT_BYTES   10240       // 128 rows * 80B
#define BUF_BYTES   40960       // 4 matrices
#define GEMM_SMEM   (2*BUF_BYTES)

template <int EPI>
__global__ __launch_bounds__(256)
void gemm_mma(const __nv_bfloat16* __restrict__ Ah, const __nv_bfloat16* __restrict__ Al,
              const __nv_bfloat16* __restrict__ Bh, const __nv_bfloat16* __restrict__ Bl,
              float* __restrict__ C,
              __nv_bfloat16* __restrict__ Chi, __nv_bfloat16* __restrict__ Clo,
              int M, int N, int K) {
    extern __shared__ char smem[];
    const int tid = threadIdx.x, lane = tid & 31, wid = tid >> 5;
    const int mBase = blockIdx.y * 128, nBase = blockIdx.x * 128;
    const int wm = wid >> 1, wn = wid & 1;
    uint32_t sbase = smem_to_u32(smem);

    float acc[2][8][4];
    #pragma unroll
    for (int i = 0; i < 2; i++)
        #pragma unroll
        for (int j = 0; j < 8; j++)
            #pragma unroll
            for (int e = 0; e < 4; e++) acc[i][j][e] = 0.f;

    const int nChunks = K >> 5;
    int idx0 = tid << 1;
    int r0 = idx0 >> 2, p0 = idx0 & 3;
    int p1 = p0 + 1;

    int aRow  = lane & 15;
    int aHalf = lane >> 4;
    int bN    = (lane & 7) | ((lane & 16) >> 1);
    int bHalf = (lane >> 3) & 1;

    const __nv_bfloat16* gmat[4] = {Ah, Al, Bh, Bl};
    int rbase[4] = {mBase, mBase, nBase, nBase};

#define PRELOAD(c) do { \
    int _b = (c) & 1; \
    uint32_t _dst = sbase + _b * BUF_BYTES; \
    int _kc = (c) << 5; \
    _Pragma("unroll") \
    for (int _m = 0; _m < 4; _m++) { \
        const char* _g = (const char*)(gmat[_m] + (size_t)(rbase[_m] + r0) * K + _kc); \
        uint32_t _d = _dst + _m * MAT_BYTES + r0 * SMEM_STRIDE; \
        CP_ASYNC16(_d + p0 * 16, _g + p0 * 16); \
        CP_ASYNC16(_d + p1 * 16, _g + p1 * 16); \
    } \
} while (0)

    PRELOAD(0);
    CP_COMMIT();

    for (int c = 0; c < nChunks; c++) {
        if (c + 1 < nChunks) { PRELOAD(c + 1); CP_COMMIT(); CP_WAIT(1); }
        else                 { CP_WAIT(0); }
        __syncthreads();

        uint32_t bufb   = sbase + (c & 1) * BUF_BYTES;
        uint32_t aHbase = bufb + (wm * 32) * SMEM_STRIDE;
        uint32_t aLbase = aHbase + MAT_BYTES;
        uint32_t bHbase = bufb + 2 * MAT_BYTES + (wn * 64) * SMEM_STRIDE;
        uint32_t bLbase = bHbase + MAT_BYTES;

        #pragma unroll
        for (int ks = 0; ks < 2; ks++) {
            int koff = ks * 32 + aHalf * 16;
            uint32_t ah[2][4], al[2][4];
            #pragma unroll
            for (int mi = 0; mi < 2; mi++) {
                uint32_t off = (mi * 16 + aRow) * SMEM_STRIDE + koff;
                ldm_x4(ah[mi], aHbase + off);
                ldm_x4(al[mi], aLbase + off);
            }
            int koffb = ks * 32 + bHalf * 16;
            #pragma unroll
            for (int np = 0; np < 4; np++) {
                uint32_t off = (np * 16 + bN) * SMEM_STRIDE + koffb;
                uint32_t bh[4], bl[4];
                ldm_x4(bh, bHbase + off);
                ldm_x4(bl, bLbase + off);
                #pragma unroll
                for (int mi = 0; mi < 2; mi++) {
                    mma_bf16(acc[mi][np*2],   ah[mi], bh);
                    mma_bf16(acc[mi][np*2+1], ah[mi], bh + 2);
                    mma_bf16(acc[mi][np*2],   al[mi], bh);
                    mma_bf16(acc[mi][np*2+1], al[mi], bh + 2);
                    mma_bf16(acc[mi][np*2],   ah[mi], bl);
                    mma_bf16(acc[mi][np*2+1], ah[mi], bl + 2);
                }
            }
        }
        __syncthreads();
    }

    int rowb = mBase + wm * 32 + (lane >> 2);
    int colb = nBase + wn * 64 + (lane & 3) * 2;
    #pragma unroll
    for (int mi = 0; mi < 2; mi++) {
        #pragma unroll
        for (int ns = 0; ns < 8; ns++) {
            int row = rowb + mi * 16;
            int col = colb + ns * 8;
            float c0 = acc[mi][ns][0], c1 = acc[mi][ns][1];
            float c2 = acc[mi][ns][2], c3 = acc[mi][ns][3];
            if (EPI == 0) {
                *reinterpret_cast<float2*>(C + (size_t)row * N + col)       = make_float2(c0, c1);
                *reinterpret_cast<float2*>(C + (size_t)(row + 8) * N + col) = make_float2(c2, c3);
            } else {
                if (EPI == 1) {
                    c0 = c0 / (1.f + __expf(-c0)); c1 = c1 / (1.f + __expf(-c1));
                    c2 = c2 / (1.f + __expf(-c2)); c3 = c3 / (1.f + __expf(-c3));
                }
                __nv_bfloat16 h0,l0,h1,l1,h2,l2,h3,l3;
                split_bf16(c0,h0,l0); split_bf16(c1,h1,l1);
                split_bf16(c2,h2,l2); split_bf16(c3,h3,l3);
                *reinterpret_cast<__nv_bfloat162*>(Chi + (size_t)row * N + col)       = __nv_bfloat162(h0, h1);
                *reinterpret_cast<__nv_bfloat162*>(Clo + (size_t)row * N + col)       = __nv_bfloat162(l0, l1);
                *reinterpret_cast<__nv_bfloat162*>(Chi + (size_t)(row + 8) * N + col) = __nv_bfloat162(h2, h3);
                *reinterpret_cast<__nv_bfloat162*>(Clo + (size_t)(row + 8) * N + col) = __nv_bfloat162(l2, l3);
            }
        }
    }
#undef PRELOAD
}

// =================== tensor-core flash attention ===========================
// grid (S/64, H, B), 128 threads (4 warps x 16 q-rows). K/V tiles of 64 keys,
// cp.async double buffered. Split-bf16: QhKh+QlKh+QhKl ; PhVh+PlVh+PhVl.
#define AST   144                  // smem row stride (64 bf16 + 16B pad)
#define AMAT  9216                 // 64 rows * 144B
#define AQH   0
#define AQL   9216
#define AKV0  18432
#define AKVSZ 36864                // 4 matrices (Kh,Kl,Vh,Vl)
#define AMSK  (18432 + 2*36864)    // 92160
#define ATT_SMEM (92160 + 512)

__global__ __launch_bounds__(128)
void attn_mma(const __nv_bfloat16* __restrict__ qh, const __nv_bfloat16* __restrict__ ql,
              const __nv_bfloat16* __restrict__ kh, const __nv_bfloat16* __restrict__ kl,
              const __nv_bfloat16* __restrict__ vh, const __nv_bfloat16* __restrict__ vl,
              const float* __restrict__ maskf,
              __nv_bfloat16* __restrict__ outh, __nv_bfloat16* __restrict__ outl) {
    extern __shared__ char smA[];
    uint32_t sb = smem_to_u32(smA);
    const int tid = threadIdx.x, lane = tid & 31, wid = tid >> 5;
    const int qt = blockIdx.x, hd = blockIdx.y, b = blockIdx.z;
    const size_t qtok0 = (size_t)b * SS + qt * 64;
    const size_t ktok0 = (size_t)b * SS;
    const int colbase = hd * DH;

    const int lrow = tid >> 1, lp0 = (tid & 1) * 4;
    const int aRow = lane & 15, aHalf = lane >> 4;
    const int bN = (lane & 7) | ((lane & 16) >> 1), bHalf = (lane >> 3) & 1;
    const int vKey = (lane & 7) + ((lane >> 4) << 3), vCol = lane & 8;

#define KV_PRELOAD(kt, bufb) do { \
    size_t _tok = ktok0 + (size_t)(kt) * 64 + lrow; \
    uint32_t _dst = sb + AKV0 + (bufb) * AKVSZ + lrow * AST + lp0 * 16; \
    const char* _s0 = (const char*)(kh + _tok * DD + colbase) + lp0 * 16; \
    const char* _s1 = (const char*)(kl + _tok * DD + colbase) + lp0 * 16; \
    const char* _s2 = (const char*)(vh + _tok * DD + colbase) + lp0 * 16; \
    const char* _s3 = (const char*)(vl + _tok * DD + colbase) + lp0 * 16; \
    _Pragma("unroll") \
    for (int _i = 0; _i < 4; _i++) { \
        CP_ASYNC16(_dst + 0*AMAT + _i*16, _s0 + _i*16); \
        CP_ASYNC16(_dst + 1*AMAT + _i*16, _s1 + _i*16); \
        CP_ASYNC16(_dst + 2*AMAT + _i*16, _s2 + _i*16); \
        CP_ASYNC16(_dst + 3*AMAT + _i*16, _s3 + _i*16); \
    } \
    if (tid < 64) CP_ASYNC4(sb + AMSK + (bufb)*256 + tid*4, maskf + b*SS + (kt)*64 + tid); \
} while (0)

    // Q tile load (64 rows x 64 cols, hi+lo)
    {
        const char* gq0 = (const char*)(qh + (qtok0 + lrow) * DD + colbase) + lp0 * 16;
        const char* gq1 = (const char*)(ql + (qtok0 + lrow) * DD + colbase) + lp0 * 16;
        uint32_t d = sb + lrow * AST + lp0 * 16;
        #pragma unroll
        for (int i = 0; i < 4; i++) {
            CP_ASYNC16(d + AQH + i*16, gq0 + i*16);
            CP_ASYNC16(d + AQL + i*16, gq1 + i*16);
        }
    }
    CP_COMMIT();
    KV_PRELOAD(0, 0);
    CP_COMMIT();

    uint32_t qhf[4][4], qlf[4][4];
    float oacc[8][4];
    #pragma unroll
    for (int i = 0; i < 8; i++)
        #pragma unroll
        for (int e = 0; e < 4; e++) oacc[i][e] = 0.f;
    float m0 = -1e30f, m1 = -1e30f, l0 = 0.f, l1 = 0.f;

    const int nTiles = SS / 64;
    for (int t = 0; t < nTiles; t++) {
        int buf = t & 1;
        if (t + 1 < nTiles) { KV_PRELOAD(t + 1, (t + 1) & 1); CP_COMMIT(); CP_WAIT(1); }
        else                { CP_WAIT(0); }
        __syncthreads();

        if (t == 0) {
            #pragma unroll
            for (int kc = 0; kc < 4; kc++) {
                uint32_t off = (wid * 16 + aRow) * AST + kc * 32 + aHalf * 16;
                ldm_x4(qhf[kc], sb + AQH + off);
                ldm_x4(qlf[kc], sb + AQL + off);
                #pragma unroll
                for (int r = 0; r < 4; r++) {
                    qhf[kc][r] = hscale8(qhf[kc][r]);
                    qlf[kc][r] = hscale8(qlf[kc][r]);
                }
            }
        }

        uint32_t kvb = sb + AKV0 + buf * AKVSZ;
        float sacc[8][4];
        #pragma unroll
        for (int i = 0; i < 8; i++)
            #pragma unroll
            for (int e = 0; e < 4; e++) sacc[i][e] = 0.f;

        // S = Q @ K^T (3 products)
        #pragma unroll
        for (int kc = 0; kc < 4; kc++) {
            #pragma unroll
            for (int nt4 = 0; nt4 < 4; nt4++) {
                uint32_t kb = kvb + (nt4 * 16 + bN) * AST + kc * 32 + bHalf * 16;
                uint32_t kf[4], kfl[4];
                ldm_x4(kf, kb);
                ldm_x4(kfl, kb + AMAT);
                mma_bf16(sacc[nt4*2],   qhf[kc], kf);
                mma_bf16(sacc[nt4*2+1], qhf[kc], kf + 2);
                mma_bf16(sacc[nt4*2],   qlf[kc], kf);
                mma_bf16(sacc[nt4*2+1], qlf[kc], kf + 2);
                mma_bf16(sacc[nt4*2],   qhf[kc], kfl);
                mma_bf16(sacc[nt4*2+1], qhf[kc], kfl + 2);
            }
        }

        // mask + online softmax
        const float* smk = (const float*)(smA + AMSK + buf * 256);
        float mx0 = -1e30f, mx1 = -1e30f;
        #pragma unroll
        for (int nt = 0; nt < 8; nt++) {
            float mk0 = smk[nt * 8 + (lane & 3) * 2];
            float mk1 = smk[nt * 8 + (lane & 3) * 2 + 1];
            if (mk0 == 0.f) { sacc[nt][0] = -1e30f; sacc[nt][2] = -1e30f; }
            if (mk1 == 0.f) { sacc[nt][1] = -1e30f; sacc[nt][3] = -1e30f; }
            mx0 = fmaxf(mx0, fmaxf(sacc[nt][0], sacc[nt][1]));
            mx1 = fmaxf(mx1, fmaxf(sacc[nt][2], sacc[nt][3]));
        }
        mx0 = fmaxf(mx0, __shfl_xor_sync(0xffffffffu, mx0, 1));
        mx0 = fmaxf(mx0, __shfl_xor_sync(0xffffffffu, mx0, 2));
        mx1 = fmaxf(mx1, __shfl_xor_sync(0xffffffffu, mx1, 1));
        mx1 = fmaxf(mx1, __shfl_xor_sync(0xffffffffu, mx1, 2));
        float mn0 = fmaxf(m0, mx0), mn1 = fmaxf(m1, mx1);
        float al0 = __expf(m0 - mn0), al1 = __expf(m1 - mn1);
        m0 = mn0; m1 = mn1;
        float ps0 = 0.f, ps1 = 0.f;
        #pragma unroll
        for (int nt = 0; nt < 8; nt++) {
            sacc[nt][0] = __expf(sacc[nt][0] - mn0);
            sacc[nt][1] = __expf(sacc[nt][1] - mn0);
            sacc[nt][2] = __expf(sacc[nt][2] - mn1);
            sacc[nt][3] = __expf(sacc[nt][3] - mn1);
            ps0 += sacc[nt][0] + sacc[nt][1];
            ps1 += sacc[nt][2] + sacc[nt][3];
        }
        l0 = l0 * al0 + ps0;
        l1 = l1 * al1 + ps1;
        #pragma unroll
        for (int nt = 0; nt < 8; nt++) {
            oacc[nt][0] *= al0; oacc[nt][1] *= al0;
            oacc[nt][2] *= al1; oacc[nt][3] *= al1;
        }

        // O += P @ V (3 products), P repacked from score fragments
        #pragma unroll
        for (int kc2 = 0; kc2 < 4; kc2++) {
            uint32_t pf[4], pfl[4];
            pf[0] = packpair(sacc[2*kc2][0],   sacc[2*kc2][1]);
            pf[1] = packpair(sacc[2*kc2][2],   sacc[2*kc2][3]);
            pf[2] = packpair(sacc[2*kc2+1][0], sacc[2*kc2+1][1]);
            pf[3] = packpair(sacc[2*kc2+1][2], sacc[2*kc2+1][3]);
            pfl[0] = packpair(bres(sacc[2*kc2][0]),   bres(sacc[2*kc2][1]));
            pfl[1] = packpair(bres(sacc[2*kc2][2]),   bres(sacc[2*kc2][3]));
            pfl[2] = packpair(bres(sacc[2*kc2+1][0]), bres(sacc[2*kc2+1][1]));
            pfl[3] = packpair(bres(sacc[2*kc2+1][2]), bres(sacc[2*kc2+1][3]));
            #pragma unroll
            for (int nt4 = 0; nt4 < 4; nt4++) {
                uint32_t va = kvb + 2*AMAT + (kc2*16 + vKey)*AST + (nt4*16 + vCol)*2;
                uint32_t vf[4], vfl[4];
                ldm_x4_t(vf, va);
                ldm_x4_t(vfl, va + AMAT);
                uint32_t b0[2]  = {vf[0],  vf[2]},  b1[2]  = {vf[1],  vf[3]};
                uint32_t b0l[2] = {vfl[0], vfl[2]}, b1l[2] = {vfl[1], vfl[3]};
                mma_bf16(oacc[nt4*2],   pf,  b0);
                mma_bf16(oacc[nt4*2+1], pf,  b1);
                mma_bf16(oacc[nt4*2],   pfl, b0);
                mma_bf16(oacc[nt4*2+1], pfl, b1);
                mma_bf16(oacc[nt4*2],   pf,  b0l);
                mma_bf16(oacc[nt4*2+1], pf,  b1l);
            }
        }
        __syncthreads();
    }

    // finalize: reduce l across quad, normalize, write bf16 hi/lo
    l0 += __shfl_xor_sync(0xffffffffu, l0, 1);
    l0 += __shfl_xor_sync(0xffffffffu, l0, 2);
    l1 += __shfl_xor_sync(0xffffffffu, l1, 1);
    l1 += __shfl_xor_sync(0xffffffffu, l1, 2);
    float inv0 = 1.f / l0, inv1 = 1.f / l1;
    size_t tok0 = qtok0 + wid * 16 + (lane >> 2);
    size_t tok1 = tok0 + 8;
    int cb = colbase + (lane & 3) * 2;
    #pragma unroll
    for (int nt = 0; nt < 8; nt++) {
        int col = cb + nt * 8;
        float f0 = oacc[nt][0] * inv0, f1 = oacc[nt][1] * inv0;
        float f2 = oacc[nt][2] * inv1, f3 = oacc[nt][3] * inv1;
        __nv_bfloat16 h0,q0,h1,q1,h2,q2,h3,q3;
        split_bf16(f0,h0,q0); split_bf16(f1,h1,q1);
        split_bf16(f2,h2,q2); split_bf16(f3,h3,q3);
        *reinterpret_cast<__nv_bfloat162*>(outh + tok0*DD + col) = __nv_bfloat162(h0, h1);
        *reinterpret_cast<__nv_bfloat162*>(outl + tok0*DD + col) = __nv_bfloat162(q0, q1);
        *reinterpret_cast<__nv_bfloat162*>(outh + tok1*DD + col) = __nv_bfloat162(h2, h3);
        *reinterpret_cast<__nv_bfloat162*>(outl + tok1*DD + col) = __nv_bfloat162(q2, q3);
    }
#undef KV_PRELOAD
}

// ---------------- pooling: deterministic two-stage ------------------------
__global__ void pool_partial(const float* __restrict__ h,
                             const float* __restrict__ maskf) {
    __shared__ float scnt[64];
    int b = blockIdx.x, chunk = blockIdx.y, tid = threadIdx.x;
    int s0 = chunk * 64;
    if (tid < 64) scnt[tid] = maskf[b * SS + s0 + tid];
    float a0 = 0.f, a1 = 0.f;
    for (int s = s0; s < s0 + 64; s++) {
        float np = maskf[b * SS + s];
        const float* hp = h + (size_t)(b * SS + s) * DD;
        a0 += hp[tid] * np;
        a1 += hp[tid + 256] * np;
    }
    g_pool[(size_t)(b * 16 + chunk) * DD + tid]       = a0;
    g_pool[(size_t)(b * 16 + chunk) * DD + tid + 256] = a1;
    __syncthreads();
    if (tid == 0) {
        float c = 0.f;
        #pragma unroll
        for (int i = 0; i < 64; i++) c += scnt[i];
        g_cnt[b * 16 + chunk] = c;
    }
}

__global__ void pool_final(const float* __restrict__ Wout,
                           const float* __restrict__ bout,
                           float* __restrict__ out) {
    __shared__ float red[40];
    int b = blockIdx.x, tid = threadIdx.x;
    float a0 = 0.f, a1 = 0.f, cnt = 0.f;
    #pragma unroll
    for (int c = 0; c < 16; c++) {
        a0 += g_pool[(size_t)(b * 16 + c) * DD + tid];
        a1 += g_pool[(size_t)(b * 16 + c) * DD + tid + 256];
        cnt += g_cnt[b * 16 + c];
    }
    float inv = 1.f / (cnt + 1e-8f);
    float p0 = a0 * inv, p1 = a1 * inv;
    for (int j = 0; j < OUTD; j++) {
        float p = p0 * Wout[tid * OUTD + j] + p1 * Wout[(tid + 256) * OUTD + j];
        float ssum = block_sum(p, red);
        if (tid == 0) out[b * OUTD + j] = ssum + bout[j];
    }
}

// ---------------- launch ---------------------------------------------------
extern "C" void kernel_launch(void* const* d_in, const int* in_sizes, int n_in,
                              void* d_out, int out_size) {
    const float* x     = (const float*)d_in[0];
    const float* Wproj = (const float*)d_in[1];
    const float* bproj = (const float*)d_in[2];
    const float* gp    = (const float*)d_in[3];
    const float* bp    = (const float*)d_in[4];
    const float* Wq    = (const float*)d_in[5];
    const float* Wk    = (const float*)d_in[6];
    const float* Wv    = (const float*)d_in[7];
    const float* Wo    = (const float*)d_in[8];
    const float* g1    = (const float*)d_in[9];
    const float* b1    = (const float*)d_in[10];
    const float* W1    = (const float*)d_in[11];
    const float* W2    = (const float*)d_in[12];
    const float* g2    = (const float*)d_in[13];
    const float* b2    = (const float*)d_in[14];
    const float* gf    = (const float*)d_in[15];
    const float* bf    = (const float*)d_in[16];
    const float* Wout  = (const float*)d_in[17];
    const float* bout  = (const float*)d_in[18];

    float *h, *tmp, *mask;
    cudaGetSymbolAddress((void**)&h,    g_h);
    cudaGetSymbolAddress((void**)&tmp,  g_tmp);
    cudaGetSymbolAddress((void**)&mask, g_mask);
    __nv_bfloat16 *hh, *hl, *aoh, *aol, *fh, *fl;
    cudaGetSymbolAddress((void**)&hh,  g_hh);  cudaGetSymbolAddress((void**)&hl,  g_hl);
    cudaGetSymbolAddress((void**)&aoh, g_aoh); cudaGetSymbolAddress((void**)&aol, g_aol);
    cudaGetSymbolAddress((void**)&fh,  g_fh);  cudaGetSymbolAddress((void**)&fl,  g_fl);
    __nv_bfloat16 *qhB,*qlB,*khB,*klB,*vhB,*vlB;
    cudaGetSymbolAddress((void**)&qhB, g_qh); cudaGetSymbolAddress((void**)&qlB, g_ql);
    cudaGetSymbolAddress((void**)&khB, g_kh); cudaGetSymbolAddress((void**)&klB, g_kl);
    cudaGetSymbolAddress((void**)&vhB, g_vh); cudaGetSymbolAddress((void**)&vlB, g_vl);
    __nv_bfloat16 *wqh,*wql,*wkh,*wkl,*wvh,*wvl,*woh,*wol,*w1h,*w1l,*w2h,*w2l;
    cudaGetSymbolAddress((void**)&wqh, g_wqh); cudaGetSymbolAddress((void**)&wql, g_wql);
    cudaGetSymbolAddress((void**)&wkh, g_wkh); cudaGetSymbolAddress((void**)&wkl, g_wkl);
    cudaGetSymbolAddress((void**)&wvh, g_wvh); cudaGetSymbolAddress((void**)&wvl, g_wvl);
    cudaGetSymbolAddress((void**)&woh, g_woh); cudaGetSymbolAddress((void**)&wol, g_wol);
    cudaGetSymbolAddress((void**)&w1h, g_w1h); cudaGetSymbolAddress((void**)&w1l, g_w1l);
    cudaGetSymbolAddress((void**)&w2h, g_w2h); cudaGetSymbolAddress((void**)&w2l, g_w2l);

    cudaFuncSetAttribute(gemm_mma<0>, cudaFuncAttributeMaxDynamicSharedMemorySize, GEMM_SMEM);
    cudaFuncSetAttribute(gemm_mma<1>, cudaFuncAttributeMaxDynamicSharedMemorySize, GEMM_SMEM);
    cudaFuncSetAttribute(gemm_mma<2>, cudaFuncAttributeMaxDynamicSharedMemorySize, GEMM_SMEM);
    cudaFuncSetAttribute(attn_mma,    cudaFuncAttributeMaxDynamicSharedMemorySize, ATT_SMEM);

    // weight prep (transpose + bf16 split)
    dim3 tb(32, 8);
    dim3 gDDp(DD/32, DD/32), gW1p(FF/32, DD/32), gW2p(DD/32, FF/32);
    for (int l = 0; l < LL; l++) {
        size_t od = (size_t)l * DD * DD, of1 = (size_t)l * FF * DD, of2 = (size_t)l * DD * FF;
        wprep_kernel<<<gDDp, tb>>>(Wq + od, wqh + od, wql + od, DD, DD);
        wprep_kernel<<<gDDp, tb>>>(Wk + od, wkh + od, wkl + od, DD, DD);
        wprep_kernel<<<gDDp, tb>>>(Wv + od, wvh + od, wvl + od, DD, DD);
        wprep_kernel<<<gDDp, tb>>>(Wo + od, woh + od, wol + od, DD, DD);
        wprep_kernel<<<gW1p, tb>>>(W1 + of1, w1h + of1, w1l + of1, DD, FF);
        wprep_kernel<<<gW2p, tb>>>(W2 + of2, w2h + of2, w2l + of2, FF, DD);
    }

    embed_kernel<<<NT, 256>>>(x, Wproj, bproj, h, mask);
    add_ln_kernel<<<NT, 256>>>(h, nullptr, gp, bp, hh, hl);

    dim3 gQ(DD / 128, NT / 128);
    dim3 gF1(FF / 128, NT / 128);
    dim3 gAttn(SS / 64, HH, BB);

    for (int l = 0; l < LL; l++) {
        size_t od = (size_t)l * DD * DD, of1 = (size_t)l * FF * DD, of2 = (size_t)l * DD * FF;
        gemm_mma<2><<<gQ, 256, GEMM_SMEM>>>(hh, hl, wqh + od, wql + od, nullptr, qhB, qlB, NT, DD, DD);
        gemm_mma<2><<<gQ, 256, GEMM_SMEM>>>(hh, hl, wkh + od, wkl + od, nullptr, khB, klB, NT, DD, DD);
        gemm_mma<2><<<gQ, 256, GEMM_SMEM>>>(hh, hl, wvh + od, wvl + od, nullptr, vhB, vlB, NT, DD, DD);
        attn_mma<<<gAttn, 128, ATT_SMEM>>>(qhB, qlB, khB, klB, vhB, vlB, mask, aoh, aol);
        gemm_mma<0><<<gQ, 256, GEMM_SMEM>>>(aoh, aol, woh + od, wol + od, tmp, nullptr, nullptr, NT, DD, DD);
        add_ln_kernel<<<NT, 256>>>(h, tmp, g1 + l * DD, b1 + l * DD, hh, hl);
        gemm_mma<1><<<gF1, 256, GEMM_SMEM>>>(hh, hl, w1h + of1, w1l + of1, nullptr, fh, fl, NT, FF, DD);
        gemm_mma<0><<<gQ, 256, GEMM_SMEM>>>(fh, fl, w2h + of2, w2l + of2, tmp, nullptr, nullptr, NT, DD, FF);
        add_ln_kernel<<<NT, 256>>>(h, tmp, g2 + l * DD, b2 + l * DD, hh, hl);
    }

    add_ln_kernel<<<NT, 256>>>(h, nullptr, gf, bf, hh, hl);
    pool_partial<<<dim3(BB, 16), 256>>>(h, mask);
    pool_final<<<BB, 256>>>(Wout, bout, (float*)d_out);
}

// round 5
// speedup vs baseline: 2.6087x; 1.1169x over previous
#include <cuda_runtime.h>
#include <cuda_bf16.h>
#include <math.h>
#include <stdint.h>

// Problem constants
#define BB 8
#define SS 1024
#define IN_DIM 3
#define DD 512
#define HH 8
#define FF 2048
#define LL 4
#define OUTD 6
#define DH 64
#define NT (BB*SS)   // 8192 tokens
#define QKVN 1536    // fused QKV output width

// ======================= PTX helpers (portable, sm_80+) ====================
__device__ __forceinline__ uint32_t smem_to_u32(const void* p) {
    uint32_t a;
    asm("{ .reg .u64 t; cvta.to.shared.u64 t, %1; cvt.u32.u64 %0, t; }" : "=r"(a) : "l"(p));
    return a;
}
#define CP_ASYNC16(dst, src) \
    asm volatile("cp.async.cg.shared.global [%0], [%1], 16;" :: "r"(dst), "l"(src))
#define CP_ASYNC4(dst, src) \
    asm volatile("cp.async.ca.shared.global [%0], [%1], 4;" :: "r"(dst), "l"(src))
#define CP_COMMIT() asm volatile("cp.async.commit_group;" ::: "memory")
#define CP_WAIT(n)  asm volatile("cp.async.wait_group %0;" :: "n"(n) : "memory")

__device__ __forceinline__ void ldm_x4(uint32_t* r, uint32_t addr) {
    asm volatile("ldmatrix.sync.aligned.m8n8.x4.shared.b16 {%0,%1,%2,%3}, [%4];"
        : "=r"(r[0]), "=r"(r[1]), "=r"(r[2]), "=r"(r[3]) : "r"(addr));
}
__device__ __forceinline__ void ldm_x4_t(uint32_t* r, uint32_t addr) {
    asm volatile("ldmatrix.sync.aligned.m8n8.x4.trans.shared.b16 {%0,%1,%2,%3}, [%4];"
        : "=r"(r[0]), "=r"(r[1]), "=r"(r[2]), "=r"(r[3]) : "r"(addr));
}
__device__ __forceinline__ void mma_bf16(float* d, const uint32_t* a, const uint32_t* b) {
    asm volatile("mma.sync.aligned.m16n8k16.row.col.f32.bf16.bf16.f32 "
        "{%0,%1,%2,%3}, {%4,%5,%6,%7}, {%8,%9}, {%0,%1,%2,%3};"
        : "+f"(d[0]), "+f"(d[1]), "+f"(d[2]), "+f"(d[3])
        : "r"(a[0]), "r"(a[1]), "r"(a[2]), "r"(a[3]), "r"(b[0]), "r"(b[1]));
}

// ---------------- scratch (device globals; no allocation allowed) ----------
__device__ float g_h  [NT*DD];
__device__ float g_tmp[NT*DD];
__device__ float g_mask[NT];
__device__ float g_pool[BB*16*DD];
__device__ float g_cnt[BB*16];
// bf16 split activations
__device__ __nv_bfloat16 g_hh [NT*DD], g_hl [NT*DD];
__device__ __nv_bfloat16 g_aoh[NT*DD], g_aol[NT*DD];
__device__ __nv_bfloat16 g_fh [NT*FF], g_fl [NT*FF];
__device__ __nv_bfloat16 g_qkvh[NT*QKVN], g_qkvl[NT*QKVN];
// bf16 split, transposed weights [N, K]
__device__ __nv_bfloat16 g_wqkvh[LL*QKVN*DD], g_wqkvl[LL*QKVN*DD];
__device__ __nv_bfloat16 g_woh[LL*DD*DD], g_wol[LL*DD*DD];
__device__ __nv_bfloat16 g_w1h[LL*FF*DD], g_w1l[LL*FF*DD];
__device__ __nv_bfloat16 g_w2h[LL*DD*FF], g_w2l[LL*DD*FF];

__device__ __forceinline__ void split_bf16(float v, __nv_bfloat16& hi, __nv_bfloat16& lo) {
    hi = __float2bfloat16(v);
    lo = __float2bfloat16(v - __bfloat162float(hi));
}
__device__ __forceinline__ uint32_t packpair(float a, float b) {
    __nv_bfloat162 t(__float2bfloat16(a), __float2bfloat16(b));
    return *reinterpret_cast<uint32_t*>(&t);
}
__device__ __forceinline__ float bres(float x) {
    return x - __bfloat162float(__float2bfloat16(x));
}
__device__ __forceinline__ uint32_t hscale8(uint32_t x) {  // *0.125 exact
    __nv_bfloat162 v = *reinterpret_cast<__nv_bfloat162*>(&x);
    __nv_bfloat162 s = __float2bfloat162_rn(0.125f);
    v = __hmul2(v, s);
    return *reinterpret_cast<uint32_t*>(&v);
}
__device__ __forceinline__ float wred_sum(float v) {
    #pragma unroll
    for (int o = 16; o > 0; o >>= 1) v += __shfl_xor_sync(0xffffffffu, v, o);
    return v;
}
__device__ __forceinline__ float block_sum(float v, float* red) {
    int lane = threadIdx.x & 31, w = threadIdx.x >> 5;
    v = wred_sum(v);
    if (lane == 0) red[w] = v;
    __syncthreads();
    if (w == 0) {
        float r = (lane < (int)(blockDim.x >> 5)) ? red[lane] : 0.f;
        r = wred_sum(r);
        if (lane == 0) red[32] = r;
    }
    __syncthreads();
    return red[32];
}

// -------- single-launch weight prep: all 24 matrices, QKV packed ----------
// grid.x = 12288 tile-blocks (3072/layer), block (32,8)
__global__ void wprep_all(const float* __restrict__ Wq, const float* __restrict__ Wk,
                          const float* __restrict__ Wv, const float* __restrict__ Wo,
                          const float* __restrict__ W1, const float* __restrict__ W2) {
    __shared__ float tile[32][33];
    int gid = blockIdx.x;
    int l = gid / 3072, r = gid % 3072;
    const float* src; __nv_bfloat16 *dh, *dl;
    int K, N, n0, k0;
    if (r < 1024) {                 // q,k,v,o : 512x512, 256 tiles each
        int widx = r >> 8, t = r & 255;
        n0 = (t & 15) * 32; k0 = (t >> 4) * 32;
        K = DD; N = DD;
        size_t wo = (size_t)l * DD * DD;
        if (widx < 3) {
            const float* ws[3] = {Wq, Wk, Wv};
            src = ws[widx] + wo;
            size_t dst = (size_t)l * QKVN * DD + (size_t)widx * DD * DD;
            dh = g_wqkvh + dst; dl = g_wqkvl + dst;
        } else {
            src = Wo + wo; dh = g_woh + wo; dl = g_wol + wo;
        }
    } else if (r < 2048) {          // W1 : [512,2048] -> [2048,512]
        int t = r - 1024;
        n0 = (t & 63) * 32; k0 = (t >> 6) * 32;
        K = DD; N = FF;
        size_t wo = (size_t)l * FF * DD;
        src = W1 + wo; dh = g_w1h + wo; dl = g_w1l + wo;
    } else {                        // W2 : [2048,512] -> [512,2048]
        int t = r - 2048;
        n0 = (t & 15) * 32; k0 = (t >> 4) * 32;
        K = FF; N = DD;
        size_t wo = (size_t)l * DD * FF;
        src = W2 + wo; dh = g_w2h + wo; dl = g_w2l + wo;
    }
    int tx = threadIdx.x, ty = threadIdx.y;
    #pragma unroll
    for (int j = 0; j < 32; j += 8)
        tile[ty + j][tx] = src[(size_t)(k0 + ty + j) * N + n0 + tx];
    __syncthreads();
    #pragma unroll
    for (int j = 0; j < 32; j += 8) {
        float v = tile[tx][ty + j];
        __nv_bfloat16 hi, lo; split_bf16(v, hi, lo);
        size_t idx = (size_t)(n0 + ty + j) * K + k0 + tx;
        dh[idx] = hi; dl[idx] = lo;
    }
}

// ---------------- embed: h = x@Wproj + bproj + PE ; mask ----------------
__global__ void embed_kernel(const float* __restrict__ x,
                             const float* __restrict__ Wp,
                             const float* __restrict__ bp,
                             float* __restrict__ h,
                             float* __restrict__ maskf) {
    int t = blockIdx.x;
    int s = t & (SS - 1);
    const float* xt = x + (size_t)t * IN_DIM;
    float x0 = xt[0], x1 = xt[1], x2 = xt[2];
    if (threadIdx.x == 0)
        maskf[t] = ((fabsf(x0) + fabsf(x1) + fabsf(x2)) == 0.f) ? 0.f : 1.f;
    #pragma unroll
    for (int r = 0; r < 2; r++) {
        int d = threadIdx.x + r * 256;
        float val = x0 * Wp[d] + x1 * Wp[DD + d] + x2 * Wp[2*DD + d] + bp[d];
        float freq = expf(-(float)(d & ~1) * (9.210340371976184f / (float)DD));
        float ang = (float)s * freq;
        val += (d & 1) ? cosf(ang) : sinf(ang);
        h[(size_t)t * DD + d] = val;
    }
}

// ------- warp-per-row add+LN; emits bf16 hi/lo. grid NT/8, 256 thr --------
__global__ __launch_bounds__(256)
void add_ln_kernel(float* __restrict__ h,
                   const float* __restrict__ add,
                   const float* __restrict__ g,
                   const float* __restrict__ bta,
                   __nv_bfloat16* __restrict__ oh,
                   __nv_bfloat16* __restrict__ ol) {
    int w = threadIdx.x >> 5, lane = threadIdx.x & 31;
    size_t t = (size_t)blockIdx.x * 8 + w;
    float* hp = h + t * DD;
    float v[16];
    float s = 0.f;
    #pragma unroll
    for (int i = 0; i < 4; i++) {
        int c = i * 128 + lane * 4;
        float4 a = *reinterpret_cast<const float4*>(hp + c);
        if (add) {
            float4 b = *reinterpret_cast<const float4*>(add + t * DD + c);
            a.x += b.x; a.y += b.y; a.z += b.z; a.w += b.w;
        }
        v[i*4+0]=a.x; v[i*4+1]=a.y; v[i*4+2]=a.z; v[i*4+3]=a.w;
        s += a.x + a.y + a.z + a.w;
    }
    float mean = wred_sum(s) * (1.f / (float)DD);
    float vs = 0.f;
    #pragma unroll
    for (int i = 0; i < 16; i++) { v[i] -= mean; vs += v[i] * v[i]; }
    float rs = rsqrtf(wred_sum(vs) * (1.f / (float)DD) + 1e-5f);
    #pragma unroll
    for (int i = 0; i < 4; i++) {
        int c = i * 128 + lane * 4;
        float4 gg = *reinterpret_cast<const float4*>(g + c);
        float4 bb = *reinterpret_cast<const float4*>(bta + c);
        float y0 = v[i*4+0] * rs * gg.x + bb.x;
        float y1 = v[i*4+1] * rs * gg.y + bb.y;
        float y2 = v[i*4+2] * rs * gg.z + bb.z;
        float y3 = v[i*4+3] * rs * gg.w + bb.w;
        *reinterpret_cast<float4*>(hp + c) = make_float4(y0, y1, y2, y3);
        __nv_bfloat16 h0,l0,h1,l1,h2,l2,h3,l3;
        split_bf16(y0,h0,l0); split_bf16(y1,h1,l1);
        split_bf16(y2,h2,l2); split_bf16(y3,h3,l3);
        *reinterpret_cast<__nv_bfloat162*>(oh + t*DD + c)     = __nv_bfloat162(h0, h1);
        *reinterpret_cast<__nv_bfloat162*>(oh + t*DD + c + 2) = __nv_bfloat162(h2, h3);
        *reinterpret_cast<__nv_bfloat162*>(ol + t*DD + c)     = __nv_bfloat162(l0, l1);
        *reinterpret_cast<__nv_bfloat162*>(ol + t*DD + c + 2) = __nv_bfloat162(l2, l3);
    }
}

// =================== warp-MMA split-bf16 GEMM ==============================
// EPI 0: fp32 C.  EPI 1: silu -> bf16 hi/lo.  EPI 2: bf16 hi/lo (no act).
#define SMEM_STRIDE 80          // bytes per row (32 bf16 + 8 pad)
#define MAT_BYTES   10240       // 128 rows * 80B
#define BUF_BYTES   40960       // 4 matrices
#define GEMM_SMEM   (2*BUF_BYTES)

template <int EPI>
__global__ __launch_bounds__(256, 2)
void gemm_mma(const __nv_bfloat16* __restrict__ Ah, const __nv_bfloat16* __restrict__ Al,
              const __nv_bfloat16* __restrict__ Bh, const __nv_bfloat16* __restrict__ Bl,
              float* __restrict__ C,
              __nv_bfloat16* __restrict__ Chi, __nv_bfloat16* __restrict__ Clo,
              int M, int N, int K) {
    extern __shared__ char smem[];
    const int tid = threadIdx.x, lane = tid & 31, wid = tid >> 5;
    const int mBase = blockIdx.y * 128, nBase = blockIdx.x * 128;
    const int wm = wid >> 1, wn = wid & 1;
    uint32_t sbase = smem_to_u32(smem);

    float acc[2][8][4];
    #pragma unroll
    for (int i = 0; i < 2; i++)
        #pragma unroll
        for (int j = 0; j < 8; j++)
            #pragma unroll
            for (int e = 0; e < 4; e++) acc[i][j][e] = 0.f;

    const int nChunks = K >> 5;
    int idx0 = tid << 1;
    int r0 = idx0 >> 2, p0 = idx0 & 3;
    int p1 = p0 + 1;

    int aRow  = lane & 15;
    int aHalf = lane >> 4;
    int bN    = (lane & 7) | ((lane & 16) >> 1);
    int bHalf = (lane >> 3) & 1;

    const __nv_bfloat16* gmat[4] = {Ah, Al, Bh, Bl};
    int rbase[4] = {mBase, mBase, nBase, nBase};

#define PRELOAD(c) do { \
    int _b = (c) & 1; \
    uint32_t _dst = sbase + _b * BUF_BYTES; \
    int _kc = (c) << 5; \
    _Pragma("unroll") \
    for (int _m = 0; _m < 4; _m++) { \
        const char* _g = (const char*)(gmat[_m] + (size_t)(rbase[_m] + r0) * K + _kc); \
        uint32_t _d = _dst + _m * MAT_BYTES + r0 * SMEM_STRIDE; \
        CP_ASYNC16(_d + p0 * 16, _g + p0 * 16); \
        CP_ASYNC16(_d + p1 * 16, _g + p1 * 16); \
    } \
} while (0)

    PRELOAD(0);
    CP_COMMIT();

    for (int c = 0; c < nChunks; c++) {
        if (c + 1 < nChunks) { PRELOAD(c + 1); CP_COMMIT(); CP_WAIT(1); }
        else                 { CP_WAIT(0); }
        __syncthreads();

        uint32_t bufb   = sbase + (c & 1) * BUF_BYTES;
        uint32_t aHbase = bufb + (wm * 32) * SMEM_STRIDE;
        uint32_t aLbase = aHbase + MAT_BYTES;
        uint32_t bHbase = bufb + 2 * MAT_BYTES + (wn * 64) * SMEM_STRIDE;
        uint32_t bLbase = bHbase + MAT_BYTES;

        #pragma unroll
        for (int ks = 0; ks < 2; ks++) {
            int koff = ks * 32 + aHalf * 16;
            uint32_t ah[2][4], al[2][4];
            #pragma unroll
            for (int mi = 0; mi < 2; mi++) {
                uint32_t off = (mi * 16 + aRow) * SMEM_STRIDE + koff;
                ldm_x4(ah[mi], aHbase + off);
                ldm_x4(al[mi], aLbase + off);
            }
            int koffb = ks * 32 + bHalf * 16;
            #pragma unroll
            for (int np = 0; np < 4; np++) {
                uint32_t off = (np * 16 + bN) * SMEM_STRIDE + koffb;
                uint32_t bh[4], bl[4];
                ldm_x4(bh, bHbase + off);
                ldm_x4(bl, bLbase + off);
                #pragma unroll
                for (int mi = 0; mi < 2; mi++) {
                    mma_bf16(acc[mi][np*2],   ah[mi], bh);
                    mma_bf16(acc[mi][np*2+1], ah[mi], bh + 2);
                    mma_bf16(acc[mi][np*2],   al[mi], bh);
                    mma_bf16(acc[mi][np*2+1], al[mi], bh + 2);
                    mma_bf16(acc[mi][np*2],   ah[mi], bl);
                    mma_bf16(acc[mi][np*2+1], ah[mi], bl + 2);
                }
            }
        }
        __syncthreads();
    }

    int rowb = mBase + wm * 32 + (lane >> 2);
    int colb = nBase + wn * 64 + (lane & 3) * 2;
    #pragma unroll
    for (int mi = 0; mi < 2; mi++) {
        #pragma unroll
        for (int ns = 0; ns < 8; ns++) {
            int row = rowb + mi * 16;
            int col = colb + ns * 8;
            float c0 = acc[mi][ns][0], c1 = acc[mi][ns][1];
            float c2 = acc[mi][ns][2], c3 = acc[mi][ns][3];
            if (EPI == 0) {
                *reinterpret_cast<float2*>(C + (size_t)row * N + col)       = make_float2(c0, c1);
                *reinterpret_cast<float2*>(C + (size_t)(row + 8) * N + col) = make_float2(c2, c3);
            } else {
                if (EPI == 1) {
                    c0 = c0 / (1.f + __expf(-c0)); c1 = c1 / (1.f + __expf(-c1));
                    c2 = c2 / (1.f + __expf(-c2)); c3 = c3 / (1.f + __expf(-c3));
                }
                __nv_bfloat16 h0,l0,h1,l1,h2,l2,h3,l3;
                split_bf16(c0,h0,l0); split_bf16(c1,h1,l1);
                split_bf16(c2,h2,l2); split_bf16(c3,h3,l3);
                *reinterpret_cast<__nv_bfloat162*>(Chi + (size_t)row * N + col)       = __nv_bfloat162(h0, h1);
                *reinterpret_cast<__nv_bfloat162*>(Clo + (size_t)row * N + col)       = __nv_bfloat162(l0, l1);
                *reinterpret_cast<__nv_bfloat162*>(Chi + (size_t)(row + 8) * N + col) = __nv_bfloat162(h2, h3);
                *reinterpret_cast<__nv_bfloat162*>(Clo + (size_t)(row + 8) * N + col) = __nv_bfloat162(l2, l3);
            }
        }
    }
#undef PRELOAD
}

// =================== tensor-core flash attention ===========================
// reads fused QKV buffer [NT, 1536] (hi/lo). grid (S/64, H, B), 128 threads.
#define AST   144                  // smem row stride (64 bf16 + 16B pad)
#define AMAT  9216                 // 64 rows * 144B
#define AQH   0
#define AQL   9216
#define AKV0  18432
#define AKVSZ 36864                // 4 matrices (Kh,Kl,Vh,Vl)
#define AMSK  (18432 + 2*36864)    // 92160
#define ATT_SMEM (92160 + 512)

__global__ __launch_bounds__(128)
void attn_mma(const __nv_bfloat16* __restrict__ qkvh, const __nv_bfloat16* __restrict__ qkvl,
              const float* __restrict__ maskf,
              __nv_bfloat16* __restrict__ outh, __nv_bfloat16* __restrict__ outl) {
    extern __shared__ char smA[];
    uint32_t sb = smem_to_u32(smA);
    const int tid = threadIdx.x, lane = tid & 31, wid = tid >> 5;
    const int qt = blockIdx.x, hd = blockIdx.y, b = blockIdx.z;
    const size_t qtok0 = (size_t)b * SS + qt * 64;
    const size_t ktok0 = (size_t)b * SS;
    const int colbase = hd * DH;

    const __nv_bfloat16* qh = qkvh + colbase;
    const __nv_bfloat16* ql = qkvl + colbase;
    const __nv_bfloat16* kh = qkvh + DD + colbase;
    const __nv_bfloat16* kl = qkvl + DD + colbase;
    const __nv_bfloat16* vh = qkvh + 2*DD + colbase;
    const __nv_bfloat16* vl = qkvl + 2*DD + colbase;

    const int lrow = tid >> 1, lp0 = (tid & 1) * 4;
    const int aRow = lane & 15, aHalf = lane >> 4;
    const int bN = (lane & 7) | ((lane & 16) >> 1), bHalf = (lane >> 3) & 1;
    const int vKey = (lane & 7) + ((lane >> 4) << 3), vCol = lane & 8;

#define KV_PRELOAD(kt, bufb) do { \
    size_t _tok = ktok0 + (size_t)(kt) * 64 + lrow; \
    uint32_t _dst = sb + AKV0 + (bufb) * AKVSZ + lrow * AST + lp0 * 16; \
    const char* _s0 = (const char*)(kh + _tok * QKVN) + lp0 * 16; \
    const char* _s1 = (const char*)(kl + _tok * QKVN) + lp0 * 16; \
    const char* _s2 = (const char*)(vh + _tok * QKVN) + lp0 * 16; \
    const char* _s3 = (const char*)(vl + _tok * QKVN) + lp0 * 16; \
    _Pragma("unroll") \
    for (int _i = 0; _i < 4; _i++) { \
        CP_ASYNC16(_dst + 0*AMAT + _i*16, _s0 + _i*16); \
        CP_ASYNC16(_dst + 1*AMAT + _i*16, _s1 + _i*16); \
        CP_ASYNC16(_dst + 2*AMAT + _i*16, _s2 + _i*16); \
        CP_ASYNC16(_dst + 3*AMAT + _i*16, _s3 + _i*16); \
    } \
    if (tid < 64) CP_ASYNC4(sb + AMSK + (bufb)*256 + tid*4, maskf + b*SS + (kt)*64 + tid); \
} while (0)

    // Q tile load (64 rows x 64 cols, hi+lo)
    {
        const char* gq0 = (const char*)(qh + (qtok0 + lrow) * QKVN) + lp0 * 16;
        const char* gq1 = (const char*)(ql + (qtok0 + lrow) * QKVN) + lp0 * 16;
        uint32_t d = sb + lrow * AST + lp0 * 16;
        #pragma unroll
        for (int i = 0; i < 4; i++) {
            CP_ASYNC16(d + AQH + i*16, gq0 + i*16);
            CP_ASYNC16(d + AQL + i*16, gq1 + i*16);
        }
    }
    CP_COMMIT();
    KV_PRELOAD(0, 0);
    CP_COMMIT();

    uint32_t qhf[4][4], qlf[4][4];
    float oacc[8][4];
    #pragma unroll
    for (int i = 0; i < 8; i++)
        #pragma unroll
        for (int e = 0; e < 4; e++) oacc[i][e] = 0.f;
    float m0 = -1e30f, m1 = -1e30f, l0 = 0.f, l1 = 0.f;

    const int nTiles = SS / 64;
    for (int t = 0; t < nTiles; t++) {
        int buf = t & 1;
        if (t + 1 < nTiles) { KV_PRELOAD(t + 1, (t + 1) & 1); CP_COMMIT(); CP_WAIT(1); }
        else                { CP_WAIT(0); }
        __syncthreads();

        if (t == 0) {
            #pragma unroll
            for (int kc = 0; kc < 4; kc++) {
                uint32_t off = (wid * 16 + aRow) * AST + kc * 32 + aHalf * 16;
                ldm_x4(qhf[kc], sb + AQH + off);
                ldm_x4(qlf[kc], sb + AQL + off);
                #pragma unroll
                for (int r = 0; r < 4; r++) {
                    qhf[kc][r] = hscale8(qhf[kc][r]);
                    qlf[kc][r] = hscale8(qlf[kc][r]);
                }
            }
        }

        uint32_t kvb = sb + AKV0 + buf * AKVSZ;
        float sacc[8][4];
        #pragma unroll
        for (int i = 0; i < 8; i++)
            #pragma unroll
            for (int e = 0; e < 4; e++) sacc[i][e] = 0.f;

        // S = Q @ K^T (3 products)
        #pragma unroll
        for (int kc = 0; kc < 4; kc++) {
            #pragma unroll
            for (int nt4 = 0; nt4 < 4; nt4++) {
                uint32_t kb = kvb + (nt4 * 16 + bN) * AST + kc * 32 + bHalf * 16;
                uint32_t kf[4], kfl[4];
                ldm_x4(kf, kb);
                ldm_x4(kfl, kb + AMAT);
                mma_bf16(sacc[nt4*2],   qhf[kc], kf);
                mma_bf16(sacc[nt4*2+1], qhf[kc], kf + 2);
                mma_bf16(sacc[nt4*2],   qlf[kc], kf);
                mma_bf16(sacc[nt4*2+1], qlf[kc], kf + 2);
                mma_bf16(sacc[nt4*2],   qhf[kc], kfl);
                mma_bf16(sacc[nt4*2+1], qhf[kc], kfl + 2);
            }
        }

        // mask + online softmax
        const float* smk = (const float*)(smA + AMSK + buf * 256);
        float mx0 = -1e30f, mx1 = -1e30f;
        #pragma unroll
        for (int nt = 0; nt < 8; nt++) {
            float mk0 = smk[nt * 8 + (lane & 3) * 2];
            float mk1 = smk[nt * 8 + (lane & 3) * 2 + 1];
            if (mk0 == 0.f) { sacc[nt][0] = -1e30f; sacc[nt][2] = -1e30f; }
            if (mk1 == 0.f) { sacc[nt][1] = -1e30f; sacc[nt][3] = -1e30f; }
            mx0 = fmaxf(mx0, fmaxf(sacc[nt][0], sacc[nt][1]));
            mx1 = fmaxf(mx1, fmaxf(sacc[nt][2], sacc[nt][3]));
        }
        mx0 = fmaxf(mx0, __shfl_xor_sync(0xffffffffu, mx0, 1));
        mx0 = fmaxf(mx0, __shfl_xor_sync(0xffffffffu, mx0, 2));
        mx1 = fmaxf(mx1, __shfl_xor_sync(0xffffffffu, mx1, 1));
        mx1 = fmaxf(mx1, __shfl_xor_sync(0xffffffffu, mx1, 2));
        float mn0 = fmaxf(m0, mx0), mn1 = fmaxf(m1, mx1);
        float al0 = __expf(m0 - mn0), al1 = __expf(m1 - mn1);
        m0 = mn0; m1 = mn1;
        float ps0 = 0.f, ps1 = 0.f;
        #pragma unroll
        for (int nt = 0; nt < 8; nt++) {
            sacc[nt][0] = __expf(sacc[nt][0] - mn0);
            sacc[nt][1] = __expf(sacc[nt][1] - mn0);
            sacc[nt][2] = __expf(sacc[nt][2] - mn1);
            sacc[nt][3] = __expf(sacc[nt][3] - mn1);
            ps0 += sacc[nt][0] + sacc[nt][1];
            ps1 += sacc[nt][2] + sacc[nt][3];
        }
        l0 = l0 * al0 + ps0;
        l1 = l1 * al1 + ps1;
        #pragma unroll
        for (int nt = 0; nt < 8; nt++) {
            oacc[nt][0] *= al0; oacc[nt][1] *= al0;
            oacc[nt][2] *= al1; oacc[nt][3] *= al1;
        }

        // O += P @ V (3 products)
        #pragma unroll
        for (int kc2 = 0; kc2 < 4; kc2++) {
            uint32_t pf[4], pfl[4];
            pf[0] = packpair(sacc[2*kc2][0],   sacc[2*kc2][1]);
            pf[1] = packpair(sacc[2*kc2][2],   sacc[2*kc2][3]);
            pf[2] = packpair(sacc[2*kc2+1][0], sacc[2*kc2+1][1]);
            pf[3] = packpair(sacc[2*kc2+1][2], sacc[2*kc2+1][3]);
            pfl[0] = packpair(bres(sacc[2*kc2][0]),   bres(sacc[2*kc2][1]));
            pfl[1] = packpair(bres(sacc[2*kc2][2]),   bres(sacc[2*kc2][3]));
            pfl[2] = packpair(bres(sacc[2*kc2+1][0]), bres(sacc[2*kc2+1][1]));
            pfl[3] = packpair(bres(sacc[2*kc2+1][2]), bres(sacc[2*kc2+1][3]));
            #pragma unroll
            for (int nt4 = 0; nt4 < 4; nt4++) {
                uint32_t va = kvb + 2*AMAT + (kc2*16 + vKey)*AST + (nt4*16 + vCol)*2;
                uint32_t vf[4], vfl[4];
                ldm_x4_t(vf, va);
                ldm_x4_t(vfl, va + AMAT);
                uint32_t b0[2]  = {vf[0],  vf[2]},  b1[2]  = {vf[1],  vf[3]};
                uint32_t b0l[2] = {vfl[0], vfl[2]}, b1l[2] = {vfl[1], vfl[3]};
                mma_bf16(oacc[nt4*2],   pf,  b0);
                mma_bf16(oacc[nt4*2+1], pf,  b1);
                mma_bf16(oacc[nt4*2],   pfl, b0);
                mma_bf16(oacc[nt4*2+1], pfl, b1);
                mma_bf16(oacc[nt4*2],   pf,  b0l);
                mma_bf16(oacc[nt4*2+1], pf,  b1l);
            }
        }
        __syncthreads();
    }

    l0 += __shfl_xor_sync(0xffffffffu, l0, 1);
    l0 += __shfl_xor_sync(0xffffffffu, l0, 2);
    l1 += __shfl_xor_sync(0xffffffffu, l1, 1);
    l1 += __shfl_xor_sync(0xffffffffu, l1, 2);
    float inv0 = 1.f / l0, inv1 = 1.f / l1;
    size_t tok0 = qtok0 + wid * 16 + (lane >> 2);
    size_t tok1 = tok0 + 8;
    int cb = colbase + (lane & 3) * 2;
    #pragma unroll
    for (int nt = 0; nt < 8; nt++) {
        int col = cb + nt * 8;
        float f0 = oacc[nt][0] * inv0, f1 = oacc[nt][1] * inv0;
        float f2 = oacc[nt][2] * inv1, f3 = oacc[nt][3] * inv1;
        __nv_bfloat16 h0,q0,h1,q1,h2,q2,h3,q3;
        split_bf16(f0,h0,q0); split_bf16(f1,h1,q1);
        split_bf16(f2,h2,q2); split_bf16(f3,h3,q3);
        *reinterpret_cast<__nv_bfloat162*>(outh + tok0*DD + col) = __nv_bfloat162(h0, h1);
        *reinterpret_cast<__nv_bfloat162*>(outl + tok0*DD + col) = __nv_bfloat162(q0, q1);
        *reinterpret_cast<__nv_bfloat162*>(outh + tok1*DD + col) = __nv_bfloat162(h2, h3);
        *reinterpret_cast<__nv_bfloat162*>(outl + tok1*DD + col) = __nv_bfloat162(q2, q3);
    }
#undef KV_PRELOAD
}

// ---------------- pooling: deterministic two-stage ------------------------
__global__ void pool_partial(const float* __restrict__ h,
                             const float* __restrict__ maskf) {
    __shared__ float scnt[64];
    int b = blockIdx.x, chunk = blockIdx.y, tid = threadIdx.x;
    int s0 = chunk * 64;
    if (tid < 64) scnt[tid] = maskf[b * SS + s0 + tid];
    float a0 = 0.f, a1 = 0.f;
    for (int s = s0; s < s0 + 64; s++) {
        float np = maskf[b * SS + s];
        const float* hp = h + (size_t)(b * SS + s) * DD;
        a0 += hp[tid] * np;
        a1 += hp[tid + 256] * np;
    }
    g_pool[(size_t)(b * 16 + chunk) * DD + tid]       = a0;
    g_pool[(size_t)(b * 16 + chunk) * DD + tid + 256] = a1;
    __syncthreads();
    if (tid == 0) {
        float c = 0.f;
        #pragma unroll
        for (int i = 0; i < 64; i++) c += scnt[i];
        g_cnt[b * 16 + chunk] = c;
    }
}

__global__ void pool_final(const float* __restrict__ Wout,
                           const float* __restrict__ bout,
                           float* __restrict__ out) {
    __shared__ float red[40];
    int b = blockIdx.x, tid = threadIdx.x;
    float a0 = 0.f, a1 = 0.f, cnt = 0.f;
    #pragma unroll
    for (int c = 0; c < 16; c++) {
        a0 += g_pool[(size_t)(b * 16 + c) * DD + tid];
        a1 += g_pool[(size_t)(b * 16 + c) * DD + tid + 256];
        cnt += g_cnt[b * 16 + c];
    }
    float inv = 1.f / (cnt + 1e-8f);
    float p0 = a0 * inv, p1 = a1 * inv;
    for (int j = 0; j < OUTD; j++) {
        float p = p0 * Wout[tid * OUTD + j] + p1 * Wout[(tid + 256) * OUTD + j];
        float ssum = block_sum(p, red);
        if (tid == 0) out[b * OUTD + j] = ssum + bout[j];
    }
}

// ---------------- launch ---------------------------------------------------
extern "C" void kernel_launch(void* const* d_in, const int* in_sizes, int n_in,
                              void* d_out, int out_size) {
    const float* x     = (const float*)d_in[0];
    const float* Wproj = (const float*)d_in[1];
    const float* bproj = (const float*)d_in[2];
    const float* gp    = (const float*)d_in[3];
    const float* bp    = (const float*)d_in[4];
    const float* Wq    = (const float*)d_in[5];
    const float* Wk    = (const float*)d_in[6];
    const float* Wv    = (const float*)d_in[7];
    const float* Wo    = (const float*)d_in[8];
    const float* g1    = (const float*)d_in[9];
    const float* b1    = (const float*)d_in[10];
    const float* W1    = (const float*)d_in[11];
    const float* W2    = (const float*)d_in[12];
    const float* g2    = (const float*)d_in[13];
    const float* b2    = (const float*)d_in[14];
    const float* gf    = (const float*)d_in[15];
    const float* bf    = (const float*)d_in[16];
    const float* Wout  = (const float*)d_in[17];
    const float* bout  = (const float*)d_in[18];

    float *h, *tmp, *mask;
    cudaGetSymbolAddress((void**)&h,    g_h);
    cudaGetSymbolAddress((void**)&tmp,  g_tmp);
    cudaGetSymbolAddress((void**)&mask, g_mask);
    __nv_bfloat16 *hh, *hl, *aoh, *aol, *fh, *fl, *qkvh, *qkvl;
    cudaGetSymbolAddress((void**)&hh,   g_hh);   cudaGetSymbolAddress((void**)&hl,   g_hl);
    cudaGetSymbolAddress((void**)&aoh,  g_aoh);  cudaGetSymbolAddress((void**)&aol,  g_aol);
    cudaGetSymbolAddress((void**)&fh,   g_fh);   cudaGetSymbolAddress((void**)&fl,   g_fl);
    cudaGetSymbolAddress((void**)&qkvh, g_qkvh); cudaGetSymbolAddress((void**)&qkvl, g_qkvl);
    __nv_bfloat16 *wqkvh,*wqkvl,*woh,*wol,*w1h,*w1l,*w2h,*w2l;
    cudaGetSymbolAddress((void**)&wqkvh, g_wqkvh); cudaGetSymbolAddress((void**)&wqkvl, g_wqkvl);
    cudaGetSymbolAddress((void**)&woh, g_woh); cudaGetSymbolAddress((void**)&wol, g_wol);
    cudaGetSymbolAddress((void**)&w1h, g_w1h); cudaGetSymbolAddress((void**)&w1l, g_w1l);
    cudaGetSymbolAddress((void**)&w2h, g_w2h); cudaGetSymbolAddress((void**)&w2l, g_w2l);

    cudaFuncSetAttribute(gemm_mma<0>, cudaFuncAttributeMaxDynamicSharedMemorySize, GEMM_SMEM);
    cudaFuncSetAttribute(gemm_mma<1>, cudaFuncAttributeMaxDynamicSharedMemorySize, GEMM_SMEM);
    cudaFuncSetAttribute(gemm_mma<2>, cudaFuncAttributeMaxDynamicSharedMemorySize, GEMM_SMEM);
    cudaFuncSetAttribute(attn_mma,    cudaFuncAttributeMaxDynamicSharedMemorySize, ATT_SMEM);

    wprep_all<<<12288, dim3(32, 8)>>>(Wq, Wk, Wv, Wo, W1, W2);

    embed_kernel<<<NT, 256>>>(x, Wproj, bproj, h, mask);
    add_ln_kernel<<<NT/8, 256>>>(h, nullptr, gp, bp, hh, hl);

    dim3 gQKV(QKVN / 128, NT / 128);
    dim3 gO(DD / 128, NT / 128);
    dim3 gF1(FF / 128, NT / 128);
    dim3 gAttn(SS / 64, HH, BB);

    for (int l = 0; l < LL; l++) {
        size_t oqkv = (size_t)l * QKVN * DD;
        size_t od = (size_t)l * DD * DD, of1 = (size_t)l * FF * DD, of2 = (size_t)l * DD * FF;
        gemm_mma<2><<<gQKV, 256, GEMM_SMEM>>>(hh, hl, wqkvh + oqkv, wqkvl + oqkv, nullptr, qkvh, qkvl, NT, QKVN, DD);
        attn_mma<<<gAttn, 128, ATT_SMEM>>>(qkvh, qkvl, mask, aoh, aol);
        gemm_mma<0><<<gO, 256, GEMM_SMEM>>>(aoh, aol, woh + od, wol + od, tmp, nullptr, nullptr, NT, DD, DD);
        add_ln_kernel<<<NT/8, 256>>>(h, tmp, g1 + l * DD, b1 + l * DD, hh, hl);
        gemm_mma<1><<<gF1, 256, GEMM_SMEM>>>(hh, hl, w1h + of1, w1l + of1, nullptr, fh, fl, NT, FF, DD);
        gemm_mma<0><<<gO, 256, GEMM_SMEM>>>(fh, fl, w2h + of2, w2l + of2, tmp, nullptr, nullptr, NT, DD, FF);
        add_ln_kernel<<<NT/8, 256>>>(h, tmp, g2 + l * DD, b2 + l * DD, hh, hl);
    }

    add_ln_kernel<<<NT/8, 256>>>(h, nullptr, gf, bf, hh, hl);
    pool_partial<<<dim3(BB, 16), 256>>>(h, mask);
    pool_final<<<BB, 256>>>(Wout, bout, (float*)d_out);
}